// round 3
// baseline (speedup 1.0000x reference)
#include <cuda_runtime.h>
#include <cstddef>

#define NB 8
#define NH 96
#define NW 96
#define NC 512
#define NCQ 64
#define NT (NB*NH*NW)   // 73728 tokens

typedef unsigned long long u64;

// ---------------- packed f32x2 helpers (sm_100+ PTX) ---------------------
__device__ __forceinline__ u64 pack_dup(float a) {
    u64 r; asm("mov.b64 %0, {%1,%1};" : "=l"(r) : "f"(a)); return r;
}
__device__ __forceinline__ u64 pack2(float lo, float hi) {
    u64 r; asm("mov.b64 %0, {%1,%2};" : "=l"(r) : "f"(lo), "f"(hi)); return r;
}
__device__ __forceinline__ void ffma2(u64& d, u64 a, u64 b) {
    asm("fma.rn.f32x2 %0, %1, %2, %3;" : "=l"(d) : "l"(a), "l"(b), "l"(d));
}
__device__ __forceinline__ float2 unpack2(u64 v) {
    float lo, hi; asm("mov.b64 {%0,%1}, %2;" : "=f"(lo), "=f"(hi) : "l"(v));
    return make_float2(lo, hi);
}

// ---------------- scratch (device globals; no runtime allocation) --------
__device__ float g_q[(size_t)NT*NCQ];          // [t][64]
__device__ float g_k[(size_t)NT*NCQ];          // [t][64]
__device__ float g_v[(size_t)NT*NC];           // [t][512]
__device__ float g_sv[(size_t)NB*NW*NH*NH];    // [b][w][h][g] logits/probs
__device__ float g_sh[(size_t)NT*NW];          // [b][h][w][u] logits/probs
__device__ float g_yv[(size_t)NT*NC];          // [t][512]

// =========================================================================
// GEMM: C[M,N] = A[M,K] @ B[K,N] + bias[N].  M%128==0, N%64==0, K%16==0.
// BM=128, BN=64, BK=16, 256 threads, 8x4 microtile -> 8x2 packed f32x2.
// A stored duplicated in smem (u64 pairs {a,a}); B pairs = adjacent columns.
// =========================================================================
__global__ __launch_bounds__(256) void gemm_bias_kernel(
    const float* __restrict__ A, const float* __restrict__ Bw,
    const float* __restrict__ bias, int dst, int N, int K)
{
    __shared__ u64    As2[128 * 16];  // [m][k] duplicated pairs, 16 KB
    __shared__ float4 Bs4[256];       // [k][n4]: 16 rows x 16 float4, 4 KB

    float* __restrict__ C = (dst == 0) ? g_q : (dst == 1) ? g_k : g_v;

    const int tid = threadIdx.x;
    const int tx = tid & 15;          // n direction, 16
    const int ty = tid >> 4;          // m direction, 16
    const size_t bm = (size_t)blockIdx.x * 128;
    const int bn = blockIdx.y * 64;

    u64 acc[8][2];
    #pragma unroll
    for (int i = 0; i < 8; i++) { acc[i][0] = 0ull; acc[i][1] = 0ull; }

    for (int k0 = 0; k0 < K; k0 += 16) {
        // A tile: 128x16 floats, two float4 per thread, store duplicated
        int idx = tid;
        #pragma unroll
        for (int it = 0; it < 2; it++, idx += 256) {
            int m = idx >> 2, k4 = idx & 3;
            float4 a4 = *(const float4*)(A + (bm + m) * K + k0 + k4 * 4);
            u64* dstp = &As2[m * 16 + k4 * 4];
            dstp[0] = pack_dup(a4.x); dstp[1] = pack_dup(a4.y);
            dstp[2] = pack_dup(a4.z); dstp[3] = pack_dup(a4.w);
        }
        // B tile: 16x64 floats = 256 float4, one per thread
        {
            int r = tid >> 4, c4 = tid & 15;
            Bs4[tid] = *(const float4*)(Bw + (size_t)(k0 + r) * N + bn + c4 * 4);
        }
        __syncthreads();

        const ulonglong2* Bs2 = (const ulonglong2*)Bs4;
        #pragma unroll
        for (int kk = 0; kk < 16; kk++) {
            ulonglong2 bv = Bs2[kk * 16 + tx];     // 2 packed pairs (4 cols)
            #pragma unroll
            for (int i = 0; i < 8; i++) {
                u64 a = As2[(ty * 8 + i) * 16 + kk];  // LDS.64, broadcast over tx
                ffma2(acc[i][0], a, bv.x);
                ffma2(acc[i][1], a, bv.y);
            }
        }
        __syncthreads();
    }

    float4 bb = *(const float4*)(bias + bn + tx * 4);
    #pragma unroll
    for (int i = 0; i < 8; i++) {
        size_t m = bm + ty * 8 + i;
        float2 p0 = unpack2(acc[i][0]);
        float2 p1 = unpack2(acc[i][1]);
        float4 o;
        o.x = p0.x + bb.x; o.y = p0.y + bb.y;
        o.z = p1.x + bb.z; o.w = p1.y + bb.w;
        *(float4*)(C + m * N + bn + tx * 4) = o;
    }
}

// =========================================================================
// Logits: per block, S[96][96] = Qrows(96x64) @ Krows(96x64)^T.
// mode 0: vertical (per (b,w), strided rows, diag masked) -> g_sv
// mode 1: horizontal (per (b,h), contiguous rows)         -> g_sh
// K stored transposed in smem so adjacent key rows form f32x2 pairs.
// =========================================================================
__global__ __launch_bounds__(256) void logits_kernel(int mode)
{
    __shared__ float Qs[96][17];    // [row][kk]
    __shared__ float Kst[16][98];   // [kk][row], row-pairs 8B-aligned

    const int tid = threadIdx.x;
    const int tx = tid & 15, ty = tid >> 4;
    const int bid = blockIdx.x;

    size_t base; int stride;
    if (mode == 0) {
        int b = bid / NW, w = bid % NW;
        base = ((size_t)b * NH * NW + w) * NCQ;   // q[b,0,w,:]
        stride = NW * NCQ;                        // step h
    } else {
        base = (size_t)bid * NW * NCQ;            // q[b,h,0,:]
        stride = NCQ;                             // step u/w
    }
    float* __restrict__ out = (mode == 0 ? g_sv : g_sh) + (size_t)bid * 96 * 96;

    u64 acc[6][3];
    #pragma unroll
    for (int i = 0; i < 6; i++) { acc[i][0] = 0ull; acc[i][1] = 0ull; acc[i][2] = 0ull; }

    for (int kc = 0; kc < NCQ; kc += 16) {
        for (int idx = tid; idx < 96 * 16; idx += 256) {
            int r = idx >> 4, c = idx & 15;
            size_t ga = base + (size_t)r * stride + kc + c;
            Qs[r][c]  = g_q[ga];
            Kst[c][r] = g_k[ga];
        }
        __syncthreads();
        #pragma unroll
        for (int kk = 0; kk < 16; kk++) {
            u64 bp[3];
            #pragma unroll
            for (int j = 0; j < 3; j++)
                bp[j] = *(const u64*)&Kst[kk][tx * 6 + 2 * j];
            #pragma unroll
            for (int i = 0; i < 6; i++) {
                u64 a = pack_dup(Qs[ty * 6 + i][kk]);
                ffma2(acc[i][0], a, bp[0]);
                ffma2(acc[i][1], a, bp[1]);
                ffma2(acc[i][2], a, bp[2]);
            }
        }
        __syncthreads();
    }

    #pragma unroll
    for (int i = 0; i < 6; i++) {
        int h = ty * 6 + i;
        #pragma unroll
        for (int j = 0; j < 3; j++) {
            float2 p = unpack2(acc[i][j]);
            int g = tx * 6 + 2 * j;
            float v0 = p.x, v1 = p.y;
            if (mode == 0 && h == g)     v0 = -1e30f;
            if (mode == 0 && h == g + 1) v1 = -1e30f;
            out[h * 96 + g]     = v0;
            out[h * 96 + g + 1] = v1;
        }
    }
}

// =========================================================================
// Softmax over the 192 concatenated logits per token; in place.
// One warp per token; 96 = 3*32 per half.
// =========================================================================
__global__ void softmax_kernel()
{
    int gw = (int)((blockIdx.x * blockDim.x + threadIdx.x) >> 5);
    int lane = threadIdx.x & 31;
    if (gw >= NT) return;
    int b = gw / (NH * NW), rem = gw % (NH * NW);
    int h = rem / NW, w = rem % NW;

    float* __restrict__ svp = g_sv + (((size_t)b * NW + w) * NH + h) * NH;  // 96 (over g)
    float* __restrict__ shp = g_sh + (size_t)gw * NW;                        // 96 (over u)

    float v[6];
    float m = -3.4e38f;
    #pragma unroll
    for (int i = 0; i < 3; i++) { v[i]     = svp[lane + 32 * i]; m = fmaxf(m, v[i]); }
    #pragma unroll
    for (int i = 0; i < 3; i++) { v[3 + i] = shp[lane + 32 * i]; m = fmaxf(m, v[3 + i]); }
    #pragma unroll
    for (int o = 16; o; o >>= 1) m = fmaxf(m, __shfl_xor_sync(0xffffffffu, m, o));

    float s = 0.f;
    #pragma unroll
    for (int i = 0; i < 6; i++) { v[i] = __expf(v[i] - m); s += v[i]; }
    #pragma unroll
    for (int o = 16; o; o >>= 1) s += __shfl_xor_sync(0xffffffffu, s, o);
    float inv = 1.0f / s;

    #pragma unroll
    for (int i = 0; i < 3; i++) svp[lane + 32 * i] = v[i] * inv;
    #pragma unroll
    for (int i = 0; i < 3; i++) shp[lane + 32 * i] = v[3 + i] * inv;
}

// =========================================================================
// PV: per block Y(96x512) = P(96x96) @ V(96x512), packed f32x2.
// mode 0: vertical   (P=av per (b,w), V rows strided)  -> g_yv
// mode 1: horizontal (P=ah per (b,h), V rows contig)   -> out = x + gamma*(yv+yh)
// =========================================================================
__global__ __launch_bounds__(256) void pv_kernel(
    const float* __restrict__ x, const float* __restrict__ gamma_p,
    float* __restrict__ out, int mode)
{
    __shared__ float  Ps[96 * 96];   // 36,864 B
    __shared__ float4 Vs4[256];      // 16 k-rows x 64 cols = 4,096 B

    const int tid = threadIdx.x;
    const int tx = tid & 15, ty = tid >> 4;
    const int bid = blockIdx.x;

    const float* __restrict__ Pb = (mode == 0 ? g_sv : g_sh) + (size_t)bid * 96 * 96;
    size_t vrow0; int vstride;
    if (mode == 0) {
        int b = bid / NW, w = bid % NW;
        vrow0 = ((size_t)b * NH * NW + w) * NC;  // v[b,0,w,:]; also yv row base
        vstride = NW * NC;                        // step g / h
    } else {
        vrow0 = (size_t)bid * NW * NC;            // v[b,h,0,:]; also out row base
        vstride = NC;                             // step u / w
    }

    for (int idx = tid; idx < 96 * 96; idx += 256) Ps[idx] = Pb[idx];
    float gam = (mode == 1) ? *gamma_p : 0.f;

    for (int nc = 0; nc < NC; nc += 64) {
        u64 acc[6][2];
        #pragma unroll
        for (int i = 0; i < 6; i++) { acc[i][0] = 0ull; acc[i][1] = 0ull; }

        for (int kc = 0; kc < 96; kc += 16) {
            __syncthreads();   // protect Vs4 (and Ps on first pass)
            {
                int r = tid >> 4, c4 = tid & 15;
                Vs4[tid] = *(const float4*)(g_v + vrow0 + (size_t)(kc + r) * vstride + nc + c4 * 4);
            }
            __syncthreads();
            const ulonglong2* Vs2 = (const ulonglong2*)Vs4;
            #pragma unroll
            for (int kk = 0; kk < 16; kk++) {
                ulonglong2 bv = Vs2[kk * 16 + tx];
                #pragma unroll
                for (int i = 0; i < 6; i++) {
                    u64 a = pack_dup(Ps[(ty * 6 + i) * 96 + kc + kk]);
                    ffma2(acc[i][0], a, bv.x);
                    ffma2(acc[i][1], a, bv.y);
                }
            }
        }

        #pragma unroll
        for (int i = 0; i < 6; i++) {
            int m = ty * 6 + i;
            size_t oidx = vrow0 + (size_t)m * vstride + nc + tx * 4;
            float2 p0 = unpack2(acc[i][0]);
            float2 p1 = unpack2(acc[i][1]);
            if (mode == 0) {
                float4 o; o.x = p0.x; o.y = p0.y; o.z = p1.x; o.w = p1.y;
                *(float4*)(g_yv + oidx) = o;
            } else {
                float4 yv = *(const float4*)(g_yv + oidx);
                float4 xx = *(const float4*)(x + oidx);
                float4 o;
                o.x = xx.x + gam * (yv.x + p0.x);
                o.y = xx.y + gam * (yv.y + p0.y);
                o.z = xx.z + gam * (yv.z + p1.x);
                o.w = xx.w + gam * (yv.w + p1.y);
                *(float4*)(out + oidx) = o;
            }
        }
    }
}

// =========================================================================
extern "C" void kernel_launch(void* const* d_in, const int* in_sizes, int n_in,
                              void* d_out, int out_size)
{
    const float* x     = (const float*)d_in[0];
    const float* Wq    = (const float*)d_in[1];
    const float* bq    = (const float*)d_in[2];
    const float* Wk    = (const float*)d_in[3];
    const float* bk    = (const float*)d_in[4];
    const float* Wv    = (const float*)d_in[5];
    const float* bv    = (const float*)d_in[6];
    const float* gamma = (const float*)d_in[7];
    float* out = (float*)d_out;
    (void)in_sizes; (void)n_in; (void)out_size;

    // Projections: M = 73728 (= 576*128)
    dim3 gqk(576, 1);
    gemm_bias_kernel<<<gqk, 256>>>(x, Wq, bq, 0, NCQ, NC);
    gemm_bias_kernel<<<gqk, 256>>>(x, Wk, bk, 1, NCQ, NC);
    dim3 gv(576, 8);
    gemm_bias_kernel<<<gv, 256>>>(x, Wv, bv, 2, NC, NC);

    // Logits
    logits_kernel<<<NB * NW, 256>>>(0);   // vertical (masked diag)
    logits_kernel<<<NB * NH, 256>>>(1);   // horizontal

    // Joint softmax over 192 logits per token (warp per token)
    softmax_kernel<<<NT / 8, 256>>>();

    // Attention-value + epilogue
    pv_kernel<<<NB * NW, 256>>>(x, gamma, out, 0);   // yv
    pv_kernel<<<NB * NH, 256>>>(x, gamma, out, 1);   // yh + gamma + residual
}

// round 4
// speedup vs baseline: 2.1069x; 2.1069x over previous
#include <cuda_runtime.h>
#include <cstddef>

#define NB 8
#define NH 96
#define NW 96
#define NC 512
#define NCQ 64
#define NT (NB*NH*NW)   // 73728 tokens

typedef unsigned long long u64;

// ---------------- scratch (device globals; no runtime allocation) --------
__device__ float g_q[(size_t)NT*NCQ];          // [t][64]
__device__ float g_k[(size_t)NT*NCQ];          // [t][64]
__device__ float g_v[(size_t)NT*NC];           // [t][512] (tf32-rounded)
__device__ float g_sv[(size_t)NB*NW*NH*NH];    // [b][w][h][g] logits/probs
__device__ float g_sh[(size_t)NT*NW];          // [b][h][w][u] logits/probs
__device__ float g_yv[(size_t)NT*NC];          // [t][512]

// ---------------- helpers ------------------------------------------------
__device__ __forceinline__ float to_tf32(float x) {
    unsigned u; asm("cvt.rna.tf32.f32 %0, %1;" : "=r"(u) : "f"(x));
    return __uint_as_float(u);
}
__device__ __forceinline__ void mma_tf32(float (&c)[4], const unsigned (&a)[4],
                                         const unsigned (&b)[2]) {
    asm volatile(
        "mma.sync.aligned.m16n8k8.row.col.f32.tf32.tf32.f32 "
        "{%0,%1,%2,%3}, {%4,%5,%6,%7}, {%8,%9}, {%0,%1,%2,%3};\n"
        : "+f"(c[0]), "+f"(c[1]), "+f"(c[2]), "+f"(c[3])
        : "r"(a[0]), "r"(a[1]), "r"(a[2]), "r"(a[3]),
          "r"(b[0]), "r"(b[1]));
}
__device__ __forceinline__ u64 pack_dup(float a) {
    u64 r; asm("mov.b64 %0, {%1,%1};" : "=l"(r) : "f"(a)); return r;
}
__device__ __forceinline__ void ffma2(u64& d, u64 a, u64 b) {
    asm("fma.rn.f32x2 %0, %1, %2, %3;" : "=l"(d) : "l"(a), "l"(b), "l"(d));
}
__device__ __forceinline__ float2 unpack2(u64 v) {
    float lo, hi; asm("mov.b64 {%0,%1}, %2;" : "=f"(lo), "=f"(hi) : "l"(v));
    return make_float2(lo, hi);
}

// =========================================================================
// Projection GEMM via tf32 mma: C = A(M,512) @ B(512,N) + bias.
// BM=128, BN=128, BK=16, 256 threads, warp grid 4m x 2n (warp tile 32x64).
// mode 0: B = [Wq | Wk] (N=128) -> g_q / g_k (fp32, no rounding)
// mode 1: B = Wv chunk (blockIdx.y*128) -> g_v (tf32-rounded)
// Fragment smem layouts are conflict-free: ldA=20, ldB=136.
// =========================================================================
__global__ __launch_bounds__(256) void proj_kernel(
    const float* __restrict__ A, const float* __restrict__ B0,
    const float* __restrict__ B1, const float* __restrict__ bias0,
    const float* __restrict__ bias1, int mode)
{
    __shared__ float As[128 * 20];
    __shared__ float Bs[16 * 136];

    const int tid  = threadIdx.x;
    const int lane = tid & 31, wid = tid >> 5;
    const int wm = wid & 3, wn = wid >> 2;   // 4 x 2 warps
    const int g = lane >> 2, t = lane & 3;
    const size_t bm = (size_t)blockIdx.x * 128;
    const int bn = (mode == 1) ? blockIdx.y * 128 : 0;

    float acc[2][8][4] = {};

    for (int k0 = 0; k0 < 512; k0 += 16) {
        // A tile 128x16 (512 float4, 2/thread)
        #pragma unroll
        for (int it = 0; it < 2; it++) {
            int idx = tid + it * 256;
            int m = idx >> 2, c = idx & 3;
            float4 a4 = *(const float4*)(A + (bm + m) * 512 + k0 + c * 4);
            *(float4*)&As[m * 20 + c * 4] = a4;
        }
        // B tile 16x128 (512 float4, 2/thread)
        #pragma unroll
        for (int it = 0; it < 2; it++) {
            int idx = tid + it * 256;
            int kr = idx >> 5, c = idx & 31;
            const float* src;
            if (mode == 0)
                src = (c < 16) ? (B0 + (size_t)(k0 + kr) * 64 + c * 4)
                               : (B1 + (size_t)(k0 + kr) * 64 + (c - 16) * 4);
            else
                src = B0 + (size_t)(k0 + kr) * 512 + bn + c * 4;
            *(float4*)&Bs[kr * 136 + c * 4] = *(const float4*)src;
        }
        __syncthreads();

        #pragma unroll
        for (int kc = 0; kc < 16; kc += 8) {
            unsigned a[2][4], b[8][2];
            #pragma unroll
            for (int i = 0; i < 2; i++) {
                int mb = wm * 32 + i * 16;
                a[i][0] = __float_as_uint(As[(mb + g)     * 20 + kc + t]);
                a[i][1] = __float_as_uint(As[(mb + g + 8) * 20 + kc + t]);
                a[i][2] = __float_as_uint(As[(mb + g)     * 20 + kc + t + 4]);
                a[i][3] = __float_as_uint(As[(mb + g + 8) * 20 + kc + t + 4]);
            }
            #pragma unroll
            for (int j = 0; j < 8; j++) {
                int nb = wn * 64 + j * 8;
                b[j][0] = __float_as_uint(Bs[(kc + t)     * 136 + nb + g]);
                b[j][1] = __float_as_uint(Bs[(kc + t + 4) * 136 + nb + g]);
            }
            #pragma unroll
            for (int i = 0; i < 2; i++)
                #pragma unroll
                for (int j = 0; j < 8; j++)
                    mma_tf32(acc[i][j], a[i], b[j]);
        }
        __syncthreads();
    }

    // Epilogue: c0,c1 at (row, 2t..2t+1); c2,c3 at (row+8)
    #pragma unroll
    for (int i = 0; i < 2; i++) {
        size_t r0 = bm + wm * 32 + i * 16 + g;
        #pragma unroll
        for (int j = 0; j < 8; j++) {
            int n = wn * 64 + j * 8 + 2 * t;   // block-local col
            if (mode == 0) {
                const float* bp = (wn == 0) ? bias0 : bias1;
                int nn = (wn == 0) ? n : (n - 64);
                float b0v = bp[nn], b1v = bp[nn + 1];
                float* dst = (wn == 0) ? g_q : g_k;
                float2 o0 = make_float2(acc[i][j][0] + b0v, acc[i][j][1] + b1v);
                float2 o1 = make_float2(acc[i][j][2] + b0v, acc[i][j][3] + b1v);
                *(float2*)(dst + r0 * 64 + nn)       = o0;
                *(float2*)(dst + (r0 + 8) * 64 + nn) = o1;
            } else {
                int gc = bn + n;
                float b0v = bias0[gc], b1v = bias0[gc + 1];
                float2 o0 = make_float2(to_tf32(acc[i][j][0] + b0v), to_tf32(acc[i][j][1] + b1v));
                float2 o1 = make_float2(to_tf32(acc[i][j][2] + b0v), to_tf32(acc[i][j][3] + b1v));
                *(float2*)(g_v + r0 * 512 + gc)       = o0;
                *(float2*)(g_v + (r0 + 8) * 512 + gc) = o1;
            }
        }
    }
}

// =========================================================================
// Logits (scalar f32x2): S[96][96] = Q(96x64) @ K(96x64)^T, full fp32.
// mode 0: vertical (per (b,w), strided, diag masked) -> g_sv
// mode 1: horizontal (per (b,h), contiguous)         -> g_sh
// =========================================================================
__global__ __launch_bounds__(256) void logits_kernel(int mode)
{
    __shared__ float Qs[96][17];
    __shared__ float Kst[16][98];

    const int tid = threadIdx.x;
    const int tx = tid & 15, ty = tid >> 4;
    const int bid = blockIdx.x;

    size_t base; int stride;
    if (mode == 0) {
        int b = bid / NW, w = bid % NW;
        base = ((size_t)b * NH * NW + w) * NCQ;
        stride = NW * NCQ;
    } else {
        base = (size_t)bid * NW * NCQ;
        stride = NCQ;
    }
    float* __restrict__ out = (mode == 0 ? g_sv : g_sh) + (size_t)bid * 96 * 96;

    u64 acc[6][3];
    #pragma unroll
    for (int i = 0; i < 6; i++) { acc[i][0] = 0ull; acc[i][1] = 0ull; acc[i][2] = 0ull; }

    for (int kc = 0; kc < NCQ; kc += 16) {
        for (int idx = tid; idx < 96 * 16; idx += 256) {
            int r = idx >> 4, c = idx & 15;
            size_t ga = base + (size_t)r * stride + kc + c;
            Qs[r][c]  = g_q[ga];
            Kst[c][r] = g_k[ga];
        }
        __syncthreads();
        #pragma unroll
        for (int kk = 0; kk < 16; kk++) {
            u64 bp[3];
            #pragma unroll
            for (int j = 0; j < 3; j++)
                bp[j] = *(const u64*)&Kst[kk][tx * 6 + 2 * j];
            #pragma unroll
            for (int i = 0; i < 6; i++) {
                u64 a = pack_dup(Qs[ty * 6 + i][kk]);
                ffma2(acc[i][0], a, bp[0]);
                ffma2(acc[i][1], a, bp[1]);
                ffma2(acc[i][2], a, bp[2]);
            }
        }
        __syncthreads();
    }

    #pragma unroll
    for (int i = 0; i < 6; i++) {
        int h = ty * 6 + i;
        #pragma unroll
        for (int j = 0; j < 3; j++) {
            float2 p = unpack2(acc[i][j]);
            int g = tx * 6 + 2 * j;
            float v0 = p.x, v1 = p.y;
            if (mode == 0 && h == g)     v0 = -1e30f;
            if (mode == 0 && h == g + 1) v1 = -1e30f;
            out[h * 96 + g]     = v0;
            out[h * 96 + g + 1] = v1;
        }
    }
}

// =========================================================================
// Softmax over 192 concatenated logits per token; writes tf32-rounded probs.
// =========================================================================
__global__ void softmax_kernel()
{
    int gw = (int)((blockIdx.x * blockDim.x + threadIdx.x) >> 5);
    int lane = threadIdx.x & 31;
    if (gw >= NT) return;
    int b = gw / (NH * NW), rem = gw % (NH * NW);
    int h = rem / NW, w = rem % NW;

    float* __restrict__ svp = g_sv + (((size_t)b * NW + w) * NH + h) * NH;
    float* __restrict__ shp = g_sh + (size_t)gw * NW;

    float v[6];
    float m = -3.4e38f;
    #pragma unroll
    for (int i = 0; i < 3; i++) { v[i]     = svp[lane + 32 * i]; m = fmaxf(m, v[i]); }
    #pragma unroll
    for (int i = 0; i < 3; i++) { v[3 + i] = shp[lane + 32 * i]; m = fmaxf(m, v[3 + i]); }
    #pragma unroll
    for (int o = 16; o; o >>= 1) m = fmaxf(m, __shfl_xor_sync(0xffffffffu, m, o));

    float s = 0.f;
    #pragma unroll
    for (int i = 0; i < 6; i++) { v[i] = __expf(v[i] - m); s += v[i]; }
    #pragma unroll
    for (int o = 16; o; o >>= 1) s += __shfl_xor_sync(0xffffffffu, s, o);
    float inv = 1.0f / s;

    #pragma unroll
    for (int i = 0; i < 3; i++) svp[lane + 32 * i] = to_tf32(v[i] * inv);
    #pragma unroll
    for (int i = 0; i < 3; i++) shp[lane + 32 * i] = to_tf32(v[3 + i] * inv);
}

// =========================================================================
// PV via tf32 mma: Y(96x128 chunk) = P(96x96) @ V(96x128 chunk).
// grid (768, 4); 256 threads; warp grid 2m x 4n (warp tile 48x32).
// mode 0: vertical   (P=av per (b,w), V rows strided)  -> g_yv
// mode 1: horizontal (P=ah per (b,h), V rows contig)   -> out = x + gam*(yv+yh)
// =========================================================================
__global__ __launch_bounds__(256) void pv_kernel(
    const float* __restrict__ x, const float* __restrict__ gamma_p,
    float* __restrict__ out, int mode)
{
    __shared__ float Ps[96 * 100];   // 38,400 B
    __shared__ float Vs[16 * 136];   //  8,704 B

    const int tid  = threadIdx.x;
    const int lane = tid & 31, wid = tid >> 5;
    const int wm = wid & 1, wn = wid >> 1;   // 2 x 4 warps
    const int g = lane >> 2, t = lane & 3;
    const int bid = blockIdx.x;
    const int nc = blockIdx.y * 128;

    const float* __restrict__ Pb = (mode == 0 ? g_sv : g_sh) + (size_t)bid * 96 * 96;
    size_t vrow0; int vstride;
    if (mode == 0) {
        int b = bid / NW, w = bid % NW;
        vrow0 = ((size_t)b * NH * NW + w) * NC;
        vstride = NW * NC;
    } else {
        vrow0 = (size_t)bid * NW * NC;
        vstride = NC;
    }

    // load P (96x96 = 2304 float4, 9/thread); probs already tf32-rounded
    #pragma unroll
    for (int it = 0; it < 9; it++) {
        int idx = tid + it * 256;
        int m = idx / 24, c = idx % 24;
        *(float4*)&Ps[m * 100 + c * 4] = *(const float4*)(Pb + m * 96 + c * 4);
    }
    float gam = (mode == 1) ? *gamma_p : 0.f;

    float acc[3][4][4] = {};

    for (int k0 = 0; k0 < 96; k0 += 16) {
        float4 vtmp[2];
        #pragma unroll
        for (int it = 0; it < 2; it++) {
            int idx = tid + it * 256;
            int kr = idx >> 5, c = idx & 31;
            vtmp[it] = *(const float4*)(g_v + vrow0 + (size_t)(k0 + kr) * vstride + nc + c * 4);
        }
        __syncthreads();   // prior compute done (first iter: P stores done)
        #pragma unroll
        for (int it = 0; it < 2; it++) {
            int idx = tid + it * 256;
            int kr = idx >> 5, c = idx & 31;
            *(float4*)&Vs[kr * 136 + c * 4] = vtmp[it];
        }
        __syncthreads();

        #pragma unroll
        for (int kc = 0; kc < 16; kc += 8) {
            unsigned a[3][4], b[4][2];
            #pragma unroll
            for (int i = 0; i < 3; i++) {
                int mb = wm * 48 + i * 16;
                a[i][0] = __float_as_uint(Ps[(mb + g)     * 100 + k0 + kc + t]);
                a[i][1] = __float_as_uint(Ps[(mb + g + 8) * 100 + k0 + kc + t]);
                a[i][2] = __float_as_uint(Ps[(mb + g)     * 100 + k0 + kc + t + 4]);
                a[i][3] = __float_as_uint(Ps[(mb + g + 8) * 100 + k0 + kc + t + 4]);
            }
            #pragma unroll
            for (int j = 0; j < 4; j++) {
                int nb = wn * 32 + j * 8;
                b[j][0] = __float_as_uint(Vs[(kc + t)     * 136 + nb + g]);
                b[j][1] = __float_as_uint(Vs[(kc + t + 4) * 136 + nb + g]);
            }
            #pragma unroll
            for (int i = 0; i < 3; i++)
                #pragma unroll
                for (int j = 0; j < 4; j++)
                    mma_tf32(acc[i][j], a[i], b[j]);
        }
    }

    // Epilogue
    #pragma unroll
    for (int i = 0; i < 3; i++) {
        int r0 = wm * 48 + i * 16 + g;
        #pragma unroll
        for (int j = 0; j < 4; j++) {
            int col = nc + wn * 32 + j * 8 + 2 * t;
            size_t o0 = vrow0 + (size_t)r0 * vstride + col;
            size_t o1 = vrow0 + (size_t)(r0 + 8) * vstride + col;
            if (mode == 0) {
                *(float2*)(g_yv + o0) = make_float2(acc[i][j][0], acc[i][j][1]);
                *(float2*)(g_yv + o1) = make_float2(acc[i][j][2], acc[i][j][3]);
            } else {
                float2 yv0 = *(const float2*)(g_yv + o0);
                float2 yv1 = *(const float2*)(g_yv + o1);
                float2 x0  = *(const float2*)(x + o0);
                float2 x1  = *(const float2*)(x + o1);
                float2 r0v = make_float2(x0.x + gam * (yv0.x + acc[i][j][0]),
                                         x0.y + gam * (yv0.y + acc[i][j][1]));
                float2 r1v = make_float2(x1.x + gam * (yv1.x + acc[i][j][2]),
                                         x1.y + gam * (yv1.y + acc[i][j][3]));
                *(float2*)(out + o0) = r0v;
                *(float2*)(out + o1) = r1v;
            }
        }
    }
}

// =========================================================================
extern "C" void kernel_launch(void* const* d_in, const int* in_sizes, int n_in,
                              void* d_out, int out_size)
{
    const float* x     = (const float*)d_in[0];
    const float* Wq    = (const float*)d_in[1];
    const float* bq    = (const float*)d_in[2];
    const float* Wk    = (const float*)d_in[3];
    const float* bk    = (const float*)d_in[4];
    const float* Wv    = (const float*)d_in[5];
    const float* bv    = (const float*)d_in[6];
    const float* gamma = (const float*)d_in[7];
    float* out = (float*)d_out;
    (void)in_sizes; (void)n_in; (void)out_size;

    // Projections (tensor cores, tf32)
    proj_kernel<<<dim3(576, 1), 256>>>(x, Wq, Wk, bq, bk, 0);         // q | k
    proj_kernel<<<dim3(576, 4), 256>>>(x, Wv, nullptr, bv, nullptr, 1); // v

    // Logits (scalar fp32 — feeds softmax, highest sensitivity)
    logits_kernel<<<NB * NW, 256>>>(0);
    logits_kernel<<<NB * NH, 256>>>(1);

    // Joint softmax (writes tf32-rounded probs)
    softmax_kernel<<<NT / 8, 256>>>();

    // Attention-value (tensor cores) + epilogue
    pv_kernel<<<dim3(NB * NW, 4), 256>>>(x, gamma, out, 0);
    pv_kernel<<<dim3(NB * NH, 4), 256>>>(x, gamma, out, 1);
}

// round 5
// speedup vs baseline: 2.5635x; 1.2167x over previous
#include <cuda_runtime.h>
#include <cstddef>

#define NB 8
#define NH 96
#define NW 96
#define NC 512
#define NCQ 64
#define NT (NB*NH*NW)   // 73728 tokens

typedef unsigned long long u64;

// ---------------- scratch (device globals; no runtime allocation) --------
__device__ float g_q[(size_t)NT*NCQ];          // [t][64]
__device__ float g_k[(size_t)NT*NCQ];          // [t][64]
__device__ float g_v[(size_t)NT*NC];           // [t][512] (tf32-rounded)
__device__ float g_sv[(size_t)NB*NW*NH*NH];    // [b][w][h][g] logits/probs
__device__ float g_sh[(size_t)NT*NW];          // [b][h][w][u] logits/probs
__device__ float g_yv[(size_t)NT*NC];          // [t][512]

// ---------------- helpers ------------------------------------------------
__device__ __forceinline__ float to_tf32(float x) {
    unsigned u; asm("cvt.rna.tf32.f32 %0, %1;" : "=r"(u) : "f"(x));
    return __uint_as_float(u);
}
__device__ __forceinline__ void mma_tf32(float (&c)[4], const unsigned (&a)[4],
                                         const unsigned (&b)[2]) {
    asm volatile(
        "mma.sync.aligned.m16n8k8.row.col.f32.tf32.tf32.f32 "
        "{%0,%1,%2,%3}, {%4,%5,%6,%7}, {%8,%9}, {%0,%1,%2,%3};\n"
        : "+f"(c[0]), "+f"(c[1]), "+f"(c[2]), "+f"(c[3])
        : "r"(a[0]), "r"(a[1]), "r"(a[2]), "r"(a[3]),
          "r"(b[0]), "r"(b[1]));
}
__device__ __forceinline__ u64 pack_dup(float a) {
    u64 r; asm("mov.b64 %0, {%1,%1};" : "=l"(r) : "f"(a)); return r;
}
__device__ __forceinline__ void ffma2(u64& d, u64 a, u64 b) {
    asm("fma.rn.f32x2 %0, %1, %2, %3;" : "=l"(d) : "l"(a), "l"(b), "l"(d));
}
__device__ __forceinline__ float2 unpack2(u64 v) {
    float lo, hi; asm("mov.b64 {%0,%1}, %2;" : "=f"(lo), "=f"(hi) : "l"(v));
    return make_float2(lo, hi);
}
__device__ __forceinline__ void cp16(float* s, const float* g) {
    unsigned sa = (unsigned)__cvta_generic_to_shared(s);
    asm volatile("cp.async.ca.shared.global [%0], [%1], 16;" :: "r"(sa), "l"(g));
}
__device__ __forceinline__ void cp_commit() {
    asm volatile("cp.async.commit_group;");
}
template<int N> __device__ __forceinline__ void cp_wait() {
    asm volatile("cp.async.wait_group %0;" :: "n"(N));
}

// =========================================================================
// Projection GEMM via tf32 mma, cp.async double-buffered.
// C = A(M,512) @ B(512,N) + bias.  BM=128, BN=128, BK=16, 256 thr,
// warp grid 4m x 2n (warp tile 32x64).
// mode 0: B = [Wq | Wk] (N=128) -> g_q / g_k (fp32)
// mode 1: B = Wv chunk (blockIdx.x*128) -> g_v (tf32-rounded)
// grid = (n_chunks, m_tiles) so same-A blocks share a wave (L2 reuse).
// =========================================================================
__global__ __launch_bounds__(256) void proj_kernel(
    const float* __restrict__ A, const float* __restrict__ B0,
    const float* __restrict__ B1, const float* __restrict__ bias0,
    const float* __restrict__ bias1, int mode)
{
    __shared__ float As[2][128 * 20];
    __shared__ float Bs[2][16 * 136];

    const int tid  = threadIdx.x;
    const int lane = tid & 31, wid = tid >> 5;
    const int wm = wid & 3, wn = wid >> 2;   // 4 x 2 warps
    const int g = lane >> 2, t = lane & 3;
    const size_t bm = (size_t)blockIdx.y * 128;
    const int bn = (mode == 1) ? blockIdx.x * 128 : 0;

    // per-thread load coordinates
    const int am0 = tid >> 2,        ac0 = (tid & 3) * 4;
    const int am1 = (tid + 256) >> 2, ac1 = ((tid + 256) & 3) * 4;
    const int bk0 = tid >> 5,        bc0 = (tid & 31) * 4;
    const int bk1 = (tid + 256) >> 5, bc1 = ((tid + 256) & 31) * 4;

    #define PROJ_ISSUE(buf, k0)                                                  \
    {                                                                            \
        cp16(&As[buf][am0 * 20 + ac0], A + (bm + am0) * 512 + (k0) + ac0);       \
        cp16(&As[buf][am1 * 20 + ac1], A + (bm + am1) * 512 + (k0) + ac1);       \
        const float* s0, *s1;                                                    \
        if (mode == 0) {                                                         \
            s0 = (bc0 < 64) ? (B0 + (size_t)((k0) + bk0) * 64 + bc0)             \
                            : (B1 + (size_t)((k0) + bk0) * 64 + bc0 - 64);       \
            s1 = (bc1 < 64) ? (B0 + (size_t)((k0) + bk1) * 64 + bc1)             \
                            : (B1 + (size_t)((k0) + bk1) * 64 + bc1 - 64);       \
        } else {                                                                 \
            s0 = B0 + (size_t)((k0) + bk0) * 512 + bn + bc0;                     \
            s1 = B0 + (size_t)((k0) + bk1) * 512 + bn + bc1;                     \
        }                                                                        \
        cp16(&Bs[buf][bk0 * 136 + bc0], s0);                                     \
        cp16(&Bs[buf][bk1 * 136 + bc1], s1);                                     \
        cp_commit();                                                             \
    }

    float acc[2][8][4] = {};

    PROJ_ISSUE(0, 0);
    int cur = 0;
    for (int k0 = 0; k0 < 512; k0 += 16) {
        if (k0 + 16 < 512) {
            PROJ_ISSUE(cur ^ 1, k0 + 16);
            cp_wait<1>();
        } else {
            cp_wait<0>();
        }
        __syncthreads();

        const float* Asc = As[cur];
        const float* Bsc = Bs[cur];
        #pragma unroll
        for (int kc = 0; kc < 16; kc += 8) {
            unsigned a[2][4], b[8][2];
            #pragma unroll
            for (int i = 0; i < 2; i++) {
                int mb = wm * 32 + i * 16;
                a[i][0] = __float_as_uint(Asc[(mb + g)     * 20 + kc + t]);
                a[i][1] = __float_as_uint(Asc[(mb + g + 8) * 20 + kc + t]);
                a[i][2] = __float_as_uint(Asc[(mb + g)     * 20 + kc + t + 4]);
                a[i][3] = __float_as_uint(Asc[(mb + g + 8) * 20 + kc + t + 4]);
            }
            #pragma unroll
            for (int j = 0; j < 8; j++) {
                int nb = wn * 64 + j * 8;
                b[j][0] = __float_as_uint(Bsc[(kc + t)     * 136 + nb + g]);
                b[j][1] = __float_as_uint(Bsc[(kc + t + 4) * 136 + nb + g]);
            }
            #pragma unroll
            for (int i = 0; i < 2; i++)
                #pragma unroll
                for (int j = 0; j < 8; j++)
                    mma_tf32(acc[i][j], a[i], b[j]);
        }
        __syncthreads();
        cur ^= 1;
    }
    #undef PROJ_ISSUE

    // Epilogue: c0,c1 at (row, 2t..2t+1); c2,c3 at (row+8)
    #pragma unroll
    for (int i = 0; i < 2; i++) {
        size_t r0 = bm + wm * 32 + i * 16 + g;
        #pragma unroll
        for (int j = 0; j < 8; j++) {
            int n = wn * 64 + j * 8 + 2 * t;   // block-local col
            if (mode == 0) {
                const float* bp = (wn == 0) ? bias0 : bias1;
                int nn = (wn == 0) ? n : (n - 64);
                float b0v = bp[nn], b1v = bp[nn + 1];
                float* dst = (wn == 0) ? g_q : g_k;
                *(float2*)(dst + r0 * 64 + nn)       = make_float2(acc[i][j][0] + b0v, acc[i][j][1] + b1v);
                *(float2*)(dst + (r0 + 8) * 64 + nn) = make_float2(acc[i][j][2] + b0v, acc[i][j][3] + b1v);
            } else {
                int gc = bn + n;
                float b0v = bias0[gc], b1v = bias0[gc + 1];
                *(float2*)(g_v + r0 * 512 + gc)       = make_float2(to_tf32(acc[i][j][0] + b0v), to_tf32(acc[i][j][1] + b1v));
                *(float2*)(g_v + (r0 + 8) * 512 + gc) = make_float2(to_tf32(acc[i][j][2] + b0v), to_tf32(acc[i][j][3] + b1v));
            }
        }
    }
}

// =========================================================================
// Logits (scalar f32x2): S[96][96] = Q(96x64) @ K(96x64)^T, full fp32.
// mode 0: vertical (per (b,w), strided, diag masked) -> g_sv
// mode 1: horizontal (per (b,h), contiguous)         -> g_sh
// =========================================================================
__global__ __launch_bounds__(256) void logits_kernel(int mode)
{
    __shared__ float Qs[96][17];
    __shared__ float Kst[16][98];

    const int tid = threadIdx.x;
    const int tx = tid & 15, ty = tid >> 4;
    const int bid = blockIdx.x;

    size_t base; int stride;
    if (mode == 0) {
        int b = bid / NW, w = bid % NW;
        base = ((size_t)b * NH * NW + w) * NCQ;
        stride = NW * NCQ;
    } else {
        base = (size_t)bid * NW * NCQ;
        stride = NCQ;
    }
    float* __restrict__ out = (mode == 0 ? g_sv : g_sh) + (size_t)bid * 96 * 96;

    u64 acc[6][3];
    #pragma unroll
    for (int i = 0; i < 6; i++) { acc[i][0] = 0ull; acc[i][1] = 0ull; acc[i][2] = 0ull; }

    for (int kc = 0; kc < NCQ; kc += 16) {
        for (int idx = tid; idx < 96 * 16; idx += 256) {
            int r = idx >> 4, c = idx & 15;
            size_t ga = base + (size_t)r * stride + kc + c;
            Qs[r][c]  = g_q[ga];
            Kst[c][r] = g_k[ga];
        }
        __syncthreads();
        #pragma unroll
        for (int kk = 0; kk < 16; kk++) {
            u64 bp[3];
            #pragma unroll
            for (int j = 0; j < 3; j++)
                bp[j] = *(const u64*)&Kst[kk][tx * 6 + 2 * j];
            #pragma unroll
            for (int i = 0; i < 6; i++) {
                u64 a = pack_dup(Qs[ty * 6 + i][kk]);
                ffma2(acc[i][0], a, bp[0]);
                ffma2(acc[i][1], a, bp[1]);
                ffma2(acc[i][2], a, bp[2]);
            }
        }
        __syncthreads();
    }

    #pragma unroll
    for (int i = 0; i < 6; i++) {
        int h = ty * 6 + i;
        #pragma unroll
        for (int j = 0; j < 3; j++) {
            float2 p = unpack2(acc[i][j]);
            int g = tx * 6 + 2 * j;
            float v0 = p.x, v1 = p.y;
            if (mode == 0 && h == g)     v0 = -1e30f;
            if (mode == 0 && h == g + 1) v1 = -1e30f;
            out[h * 96 + g]     = v0;
            out[h * 96 + g + 1] = v1;
        }
    }
}

// =========================================================================
// Softmax over 192 concatenated logits per token; writes tf32-rounded probs.
// =========================================================================
__global__ void softmax_kernel()
{
    int gw = (int)((blockIdx.x * blockDim.x + threadIdx.x) >> 5);
    int lane = threadIdx.x & 31;
    if (gw >= NT) return;
    int b = gw / (NH * NW), rem = gw % (NH * NW);
    int h = rem / NW, w = rem % NW;

    float* __restrict__ svp = g_sv + (((size_t)b * NW + w) * NH + h) * NH;
    float* __restrict__ shp = g_sh + (size_t)gw * NW;

    float v[6];
    float m = -3.4e38f;
    #pragma unroll
    for (int i = 0; i < 3; i++) { v[i]     = svp[lane + 32 * i]; m = fmaxf(m, v[i]); }
    #pragma unroll
    for (int i = 0; i < 3; i++) { v[3 + i] = shp[lane + 32 * i]; m = fmaxf(m, v[3 + i]); }
    #pragma unroll
    for (int o = 16; o; o >>= 1) m = fmaxf(m, __shfl_xor_sync(0xffffffffu, m, o));

    float s = 0.f;
    #pragma unroll
    for (int i = 0; i < 6; i++) { v[i] = __expf(v[i] - m); s += v[i]; }
    #pragma unroll
    for (int o = 16; o; o >>= 1) s += __shfl_xor_sync(0xffffffffu, s, o);
    float inv = 1.0f / s;

    #pragma unroll
    for (int i = 0; i < 3; i++) svp[lane + 32 * i] = to_tf32(v[i] * inv);
    #pragma unroll
    for (int i = 0; i < 3; i++) shp[lane + 32 * i] = to_tf32(v[3 + i] * inv);
}

// =========================================================================
// PV via tf32 mma: Y(96x512) = P(96x96) @ V(96x512); P loaded ONCE per
// block, 4 internal n-chunks of 128. 256 thr; warp grid 2m x 4n (48x32).
// mode 0: vertical   (P=av per (b,w), V rows strided)  -> g_yv
// mode 1: horizontal (P=ah per (b,h), V rows contig)   -> out = x + gam*(yv+yh)
// =========================================================================
__global__ __launch_bounds__(256) void pv_kernel(
    const float* __restrict__ x, const float* __restrict__ gamma_p,
    float* __restrict__ out, int mode)
{
    __shared__ float Ps[96 * 100];   // 38,400 B
    __shared__ float Vs[16 * 136];   //  8,704 B

    const int tid  = threadIdx.x;
    const int lane = tid & 31, wid = tid >> 5;
    const int wm = wid & 1, wn = wid >> 1;   // 2 x 4 warps
    const int g = lane >> 2, t = lane & 3;
    const int bid = blockIdx.x;

    const float* __restrict__ Pb = (mode == 0 ? g_sv : g_sh) + (size_t)bid * 96 * 96;
    size_t vrow0; int vstride;
    if (mode == 0) {
        int b = bid / NW, w = bid % NW;
        vrow0 = ((size_t)b * NH * NW + w) * NC;
        vstride = NW * NC;
    } else {
        vrow0 = (size_t)bid * NW * NC;
        vstride = NC;
    }

    // load P once (96x96 = 2304 float4, 9/thread); probs already tf32-rounded
    #pragma unroll
    for (int it = 0; it < 9; it++) {
        int idx = tid + it * 256;
        int m = idx / 24, c = idx % 24;
        *(float4*)&Ps[m * 100 + c * 4] = *(const float4*)(Pb + m * 96 + c * 4);
    }
    float gam = (mode == 1) ? *gamma_p : 0.f;

    const int vk0 = tid >> 5,         vc0 = (tid & 31) * 4;
    const int vk1 = (tid + 256) >> 5, vc1 = ((tid + 256) & 31) * 4;

    for (int nc = 0; nc < NC; nc += 128) {
        float acc[3][4][4] = {};

        for (int k0 = 0; k0 < 96; k0 += 16) {
            // register prefetch (issued while others may still be computing)
            float4 vt0 = *(const float4*)(g_v + vrow0 + (size_t)(k0 + vk0) * vstride + nc + vc0);
            float4 vt1 = *(const float4*)(g_v + vrow0 + (size_t)(k0 + vk1) * vstride + nc + vc1);
            __syncthreads();   // prior compute done with Vs (first iter: Ps stores done)
            *(float4*)&Vs[vk0 * 136 + vc0] = vt0;
            *(float4*)&Vs[vk1 * 136 + vc1] = vt1;
            __syncthreads();

            #pragma unroll
            for (int kc = 0; kc < 16; kc += 8) {
                unsigned a[3][4], b[4][2];
                #pragma unroll
                for (int i = 0; i < 3; i++) {
                    int mb = wm * 48 + i * 16;
                    a[i][0] = __float_as_uint(Ps[(mb + g)     * 100 + k0 + kc + t]);
                    a[i][1] = __float_as_uint(Ps[(mb + g + 8) * 100 + k0 + kc + t]);
                    a[i][2] = __float_as_uint(Ps[(mb + g)     * 100 + k0 + kc + t + 4]);
                    a[i][3] = __float_as_uint(Ps[(mb + g + 8) * 100 + k0 + kc + t + 4]);
                }
                #pragma unroll
                for (int j = 0; j < 4; j++) {
                    int nb = wn * 32 + j * 8;
                    b[j][0] = __float_as_uint(Vs[(kc + t)     * 136 + nb + g]);
                    b[j][1] = __float_as_uint(Vs[(kc + t + 4) * 136 + nb + g]);
                }
                #pragma unroll
                for (int i = 0; i < 3; i++)
                    #pragma unroll
                    for (int j = 0; j < 4; j++)
                        mma_tf32(acc[i][j], a[i], b[j]);
            }
        }

        // Epilogue for this n-chunk
        #pragma unroll
        for (int i = 0; i < 3; i++) {
            int r0 = wm * 48 + i * 16 + g;
            #pragma unroll
            for (int j = 0; j < 4; j++) {
                int col = nc + wn * 32 + j * 8 + 2 * t;
                size_t o0 = vrow0 + (size_t)r0 * vstride + col;
                size_t o1 = vrow0 + (size_t)(r0 + 8) * vstride + col;
                if (mode == 0) {
                    *(float2*)(g_yv + o0) = make_float2(acc[i][j][0], acc[i][j][1]);
                    *(float2*)(g_yv + o1) = make_float2(acc[i][j][2], acc[i][j][3]);
                } else {
                    float2 yv0 = *(const float2*)(g_yv + o0);
                    float2 yv1 = *(const float2*)(g_yv + o1);
                    float2 x0  = *(const float2*)(x + o0);
                    float2 x1  = *(const float2*)(x + o1);
                    *(float2*)(out + o0) = make_float2(x0.x + gam * (yv0.x + acc[i][j][0]),
                                                       x0.y + gam * (yv0.y + acc[i][j][1]));
                    *(float2*)(out + o1) = make_float2(x1.x + gam * (yv1.x + acc[i][j][2]),
                                                       x1.y + gam * (yv1.y + acc[i][j][3]));
                }
            }
        }
    }
}

// =========================================================================
extern "C" void kernel_launch(void* const* d_in, const int* in_sizes, int n_in,
                              void* d_out, int out_size)
{
    const float* x     = (const float*)d_in[0];
    const float* Wq    = (const float*)d_in[1];
    const float* bq    = (const float*)d_in[2];
    const float* Wk    = (const float*)d_in[3];
    const float* bk    = (const float*)d_in[4];
    const float* Wv    = (const float*)d_in[5];
    const float* bv    = (const float*)d_in[6];
    const float* gamma = (const float*)d_in[7];
    float* out = (float*)d_out;
    (void)in_sizes; (void)n_in; (void)out_size;

    // Projections (tensor cores, tf32, cp.async pipelined)
    proj_kernel<<<dim3(1, 576), 256>>>(x, Wq, Wk, bq, bk, 0);           // q | k
    proj_kernel<<<dim3(4, 576), 256>>>(x, Wv, nullptr, bv, nullptr, 1); // v

    // Logits (scalar fp32 — feeds softmax, highest sensitivity)
    logits_kernel<<<NB * NW, 256>>>(0);
    logits_kernel<<<NB * NH, 256>>>(1);

    // Joint softmax (writes tf32-rounded probs)
    softmax_kernel<<<NT / 8, 256>>>();

    // Attention-value (tensor cores) + epilogue
    pv_kernel<<<NB * NW, 256>>>(x, gamma, out, 0);
    pv_kernel<<<NB * NH, 256>>>(x, gamma, out, 1);
}

// round 7
// speedup vs baseline: 2.7562x; 1.0751x over previous
#include <cuda_runtime.h>
#include <cstddef>

#define NB 8
#define NH 96
#define NW 96
#define NC 512
#define NCQ 64
#define NT (NB*NH*NW)   // 73728 tokens

typedef unsigned long long u64;

// ---------------- scratch (device globals; no runtime allocation) --------
__device__ float g_q[(size_t)NT*NCQ];          // [t][64]
__device__ float g_k[(size_t)NT*NCQ];          // [t][64]
__device__ float g_v[(size_t)NT*NC];           // [t][512] (tf32-rounded)
__device__ float g_sv[(size_t)NB*NW*NH*NH];    // [b][w][h][g] logits/probs
__device__ float g_sh[(size_t)NT*NW];          // [b][h][w][u] logits/probs
__device__ float g_yv[(size_t)NT*NC];          // [t][512]

// ---------------- helpers ------------------------------------------------
__device__ __forceinline__ float to_tf32(float x) {
    unsigned u; asm("cvt.rna.tf32.f32 %0, %1;" : "=r"(u) : "f"(x));
    return __uint_as_float(u);
}
__device__ __forceinline__ void mma_tf32(float (&c)[4], const unsigned (&a)[4],
                                         const unsigned (&b)[2]) {
    asm volatile(
        "mma.sync.aligned.m16n8k8.row.col.f32.tf32.tf32.f32 "
        "{%0,%1,%2,%3}, {%4,%5,%6,%7}, {%8,%9}, {%0,%1,%2,%3};\n"
        : "+f"(c[0]), "+f"(c[1]), "+f"(c[2]), "+f"(c[3])
        : "r"(a[0]), "r"(a[1]), "r"(a[2]), "r"(a[3]),
          "r"(b[0]), "r"(b[1]));
}
__device__ __forceinline__ u64 pack_dup(float a) {
    u64 r; asm("mov.b64 %0, {%1,%1};" : "=l"(r) : "f"(a)); return r;
}
__device__ __forceinline__ void ffma2(u64& d, u64 a, u64 b) {
    asm("fma.rn.f32x2 %0, %1, %2, %3;" : "=l"(d) : "l"(a), "l"(b), "l"(d));
}
__device__ __forceinline__ float2 unpack2(u64 v) {
    float lo, hi; asm("mov.b64 {%0,%1}, %2;" : "=f"(lo), "=f"(hi) : "l"(v));
    return make_float2(lo, hi);
}
__device__ __forceinline__ void cp16(void* s, const void* g) {
    unsigned sa = (unsigned)__cvta_generic_to_shared(s);
    asm volatile("cp.async.ca.shared.global [%0], [%1], 16;" :: "r"(sa), "l"(g));
}
__device__ __forceinline__ void cp_commit() {
    asm volatile("cp.async.commit_group;");
}
template<int N> __device__ __forceinline__ void cp_wait() {
    asm volatile("cp.async.wait_group %0;" :: "n"(N));
}

// =========================================================================
// Projection GEMM via tf32 mma, cp.async double-buffered.
// C = A(M,512) @ B(512,N) + bias.  BM=128, BN=128, BK=16, 256 thr,
// warp grid 4m x 2n (warp tile 32x64).
// mode 0: B = [Wq | Wk] (N=128) -> g_q / g_k (fp32)
// mode 1: B = Wv chunk (blockIdx.x*128) -> g_v (tf32-rounded)
// grid = (n_chunks, m_tiles) so same-A blocks share a wave (L2 reuse).
// =========================================================================
__global__ __launch_bounds__(256) void proj_kernel(
    const float* __restrict__ A, const float* __restrict__ B0,
    const float* __restrict__ B1, const float* __restrict__ bias0,
    const float* __restrict__ bias1, int mode)
{
    __shared__ float As[2][128 * 20];
    __shared__ float Bs[2][16 * 136];

    const int tid  = threadIdx.x;
    const int lane = tid & 31, wid = tid >> 5;
    const int wm = wid & 3, wn = wid >> 2;   // 4 x 2 warps
    const int g = lane >> 2, t = lane & 3;
    const size_t bm = (size_t)blockIdx.y * 128;
    const int bn = (mode == 1) ? blockIdx.x * 128 : 0;

    const int am0 = tid >> 2,         ac0 = (tid & 3) * 4;
    const int am1 = (tid + 256) >> 2, ac1 = ((tid + 256) & 3) * 4;
    const int bk0 = tid >> 5,         bc0 = (tid & 31) * 4;
    const int bk1 = (tid + 256) >> 5, bc1 = ((tid + 256) & 31) * 4;

    #define PROJ_ISSUE(buf, k0)                                                  \
    {                                                                            \
        cp16(&As[buf][am0 * 20 + ac0], A + (bm + am0) * 512 + (k0) + ac0);       \
        cp16(&As[buf][am1 * 20 + ac1], A + (bm + am1) * 512 + (k0) + ac1);       \
        const float* s0, *s1;                                                    \
        if (mode == 0) {                                                         \
            s0 = (bc0 < 64) ? (B0 + (size_t)((k0) + bk0) * 64 + bc0)             \
                            : (B1 + (size_t)((k0) + bk0) * 64 + bc0 - 64);       \
            s1 = (bc1 < 64) ? (B0 + (size_t)((k0) + bk1) * 64 + bc1)             \
                            : (B1 + (size_t)((k0) + bk1) * 64 + bc1 - 64);       \
        } else {                                                                 \
            s0 = B0 + (size_t)((k0) + bk0) * 512 + bn + bc0;                     \
            s1 = B0 + (size_t)((k0) + bk1) * 512 + bn + bc1;                     \
        }                                                                        \
        cp16(&Bs[buf][bk0 * 136 + bc0], s0);                                     \
        cp16(&Bs[buf][bk1 * 136 + bc1], s1);                                     \
        cp_commit();                                                             \
    }

    float acc[2][8][4] = {};

    PROJ_ISSUE(0, 0);
    int cur = 0;
    for (int k0 = 0; k0 < 512; k0 += 16) {
        if (k0 + 16 < 512) { PROJ_ISSUE(cur ^ 1, k0 + 16); cp_wait<1>(); }
        else               { cp_wait<0>(); }
        __syncthreads();

        const float* Asc = As[cur];
        const float* Bsc = Bs[cur];
        #pragma unroll
        for (int kc = 0; kc < 16; kc += 8) {
            unsigned a[2][4], b[8][2];
            #pragma unroll
            for (int i = 0; i < 2; i++) {
                int mb = wm * 32 + i * 16;
                a[i][0] = __float_as_uint(Asc[(mb + g)     * 20 + kc + t]);
                a[i][1] = __float_as_uint(Asc[(mb + g + 8) * 20 + kc + t]);
                a[i][2] = __float_as_uint(Asc[(mb + g)     * 20 + kc + t + 4]);
                a[i][3] = __float_as_uint(Asc[(mb + g + 8) * 20 + kc + t + 4]);
            }
            #pragma unroll
            for (int j = 0; j < 8; j++) {
                int nb = wn * 64 + j * 8;
                b[j][0] = __float_as_uint(Bsc[(kc + t)     * 136 + nb + g]);
                b[j][1] = __float_as_uint(Bsc[(kc + t + 4) * 136 + nb + g]);
            }
            #pragma unroll
            for (int i = 0; i < 2; i++)
                #pragma unroll
                for (int j = 0; j < 8; j++)
                    mma_tf32(acc[i][j], a[i], b[j]);
        }
        __syncthreads();
        cur ^= 1;
    }
    #undef PROJ_ISSUE

    // Epilogue: c0,c1 at (row, 2t..2t+1); c2,c3 at (row+8)
    #pragma unroll
    for (int i = 0; i < 2; i++) {
        size_t r0 = bm + wm * 32 + i * 16 + g;
        #pragma unroll
        for (int j = 0; j < 8; j++) {
            int n = wn * 64 + j * 8 + 2 * t;   // block-local col
            if (mode == 0) {
                const float* bp = (wn == 0) ? bias0 : bias1;
                int nn = (wn == 0) ? n : (n - 64);
                float b0v = bp[nn], b1v = bp[nn + 1];
                float* dst = (wn == 0) ? g_q : g_k;
                *(float2*)(dst + r0 * 64 + nn)       = make_float2(acc[i][j][0] + b0v, acc[i][j][1] + b1v);
                *(float2*)(dst + (r0 + 8) * 64 + nn) = make_float2(acc[i][j][2] + b0v, acc[i][j][3] + b1v);
            } else {
                int gc = bn + n;
                float b0v = bias0[gc], b1v = bias0[gc + 1];
                *(float2*)(g_v + r0 * 512 + gc)       = make_float2(to_tf32(acc[i][j][0] + b0v), to_tf32(acc[i][j][1] + b1v));
                *(float2*)(g_v + (r0 + 8) * 512 + gc) = make_float2(to_tf32(acc[i][j][2] + b0v), to_tf32(acc[i][j][3] + b1v));
            }
        }
    }
}

// =========================================================================
// Logits (scalar f32x2): S[96][96] = Q(96x64) @ K(96x64)^T, full fp32.
// mode 0: vertical (per (b,w), strided, diag masked) -> g_sv
// mode 1: horizontal (per (b,h), contiguous)         -> g_sh
// =========================================================================
__global__ __launch_bounds__(256) void logits_kernel(int mode)
{
    __shared__ float Qs[96][17];
    __shared__ float Kst[16][98];

    const int tid = threadIdx.x;
    const int tx = tid & 15, ty = tid >> 4;
    const int bid = blockIdx.x;

    size_t base; int stride;
    if (mode == 0) {
        int b = bid / NW, w = bid % NW;
        base = ((size_t)b * NH * NW + w) * NCQ;
        stride = NW * NCQ;
    } else {
        base = (size_t)bid * NW * NCQ;
        stride = NCQ;
    }
    float* __restrict__ out = (mode == 0 ? g_sv : g_sh) + (size_t)bid * 96 * 96;

    u64 acc[6][3];
    #pragma unroll
    for (int i = 0; i < 6; i++) { acc[i][0] = 0ull; acc[i][1] = 0ull; acc[i][2] = 0ull; }

    for (int kc = 0; kc < NCQ; kc += 16) {
        for (int idx = tid; idx < 96 * 16; idx += 256) {
            int r = idx >> 4, c = idx & 15;
            size_t ga = base + (size_t)r * stride + kc + c;
            Qs[r][c]  = g_q[ga];
            Kst[c][r] = g_k[ga];
        }
        __syncthreads();
        #pragma unroll
        for (int kk = 0; kk < 16; kk++) {
            u64 bp[3];
            #pragma unroll
            for (int j = 0; j < 3; j++)
                bp[j] = *(const u64*)&Kst[kk][tx * 6 + 2 * j];
            #pragma unroll
            for (int i = 0; i < 6; i++) {
                u64 a = pack_dup(Qs[ty * 6 + i][kk]);
                ffma2(acc[i][0], a, bp[0]);
                ffma2(acc[i][1], a, bp[1]);
                ffma2(acc[i][2], a, bp[2]);
            }
        }
        __syncthreads();
    }

    #pragma unroll
    for (int i = 0; i < 6; i++) {
        int h = ty * 6 + i;
        #pragma unroll
        for (int j = 0; j < 3; j++) {
            float2 p = unpack2(acc[i][j]);
            int g = tx * 6 + 2 * j;
            float v0 = p.x, v1 = p.y;
            if (mode == 0 && h == g)     v0 = -1e30f;
            if (mode == 0 && h == g + 1) v1 = -1e30f;
            out[h * 96 + g]     = v0;
            out[h * 96 + g + 1] = v1;
        }
    }
}

// =========================================================================
// Softmax over 192 concatenated logits per token; writes tf32-rounded probs.
// =========================================================================
__global__ void softmax_kernel()
{
    int gw = (int)((blockIdx.x * blockDim.x + threadIdx.x) >> 5);
    int lane = threadIdx.x & 31;
    if (gw >= NT) return;
    int b = gw / (NH * NW), rem = gw % (NH * NW);
    int h = rem / NW, w = rem % NW;

    float* __restrict__ svp = g_sv + (((size_t)b * NW + w) * NH + h) * NH;
    float* __restrict__ shp = g_sh + (size_t)gw * NW;

    float v[6];
    float m = -3.4e38f;
    #pragma unroll
    for (int i = 0; i < 3; i++) { v[i]     = svp[lane + 32 * i]; m = fmaxf(m, v[i]); }
    #pragma unroll
    for (int i = 0; i < 3; i++) { v[3 + i] = shp[lane + 32 * i]; m = fmaxf(m, v[3 + i]); }
    #pragma unroll
    for (int o = 16; o; o >>= 1) m = fmaxf(m, __shfl_xor_sync(0xffffffffu, m, o));

    float s = 0.f;
    #pragma unroll
    for (int i = 0; i < 6; i++) { v[i] = __expf(v[i] - m); s += v[i]; }
    #pragma unroll
    for (int o = 16; o; o >>= 1) s += __shfl_xor_sync(0xffffffffu, s, o);
    float inv = 1.0f / s;

    #pragma unroll
    for (int i = 0; i < 3; i++) svp[lane + 32 * i] = to_tf32(v[i] * inv);
    #pragma unroll
    for (int i = 0; i < 3; i++) shp[lane + 32 * i] = to_tf32(v[3 + i] * inv);
}

// =========================================================================
// PV via tf32 mma, cp.async double-buffered V tiles.
// Y(96x512) = P(96x96) @ V(96x512); P loaded once per block,
// 4 internal n-chunks of 128. 256 thr; warp grid 2m x 4n (48x32).
// mode 0: vertical   (P=av per (b,w), V rows strided)  -> g_yv
// mode 1: horizontal (P=ah per (b,h), V rows contig)   -> out = x + gam*(yv+yh)
// =========================================================================
__global__ __launch_bounds__(256) void pv_kernel(
    const float* __restrict__ x, const float* __restrict__ gamma_p,
    float* __restrict__ out, int mode)
{
    __shared__ float Ps[96 * 100];      // 38,400 B
    __shared__ float Vs[2][16 * 136];   // 2 x 8,704 B

    const int tid  = threadIdx.x;
    const int lane = tid & 31, wid = tid >> 5;
    const int wm = wid & 1, wn = wid >> 1;   // 2 x 4 warps
    const int g = lane >> 2, t = lane & 3;
    const int bid = blockIdx.x;

    const float* __restrict__ Pb = (mode == 0 ? g_sv : g_sh) + (size_t)bid * 96 * 96;
    size_t vrow0; int vstride;
    if (mode == 0) {
        int b = bid / NW, w = bid % NW;
        vrow0 = ((size_t)b * NH * NW + w) * NC;
        vstride = NW * NC;
    } else {
        vrow0 = (size_t)bid * NW * NC;
        vstride = NC;
    }

    // load P once (96x96 = 2304 float4, 9/thread); probs already tf32-rounded
    #pragma unroll
    for (int it = 0; it < 9; it++) {
        int idx = tid + it * 256;
        int m = idx / 24, c = idx % 24;
        *(float4*)&Ps[m * 100 + c * 4] = *(const float4*)(Pb + m * 96 + c * 4);
    }
    float gam = (mode == 1) ? *gamma_p : 0.f;

    // V tile: 16 rows x 128 cols = 512 float4, 2/thread
    const int vk0 = tid >> 5,         vc0 = (tid & 31) * 4;
    const int vk1 = (tid + 256) >> 5, vc1 = ((tid + 256) & 31) * 4;

    #define PVV_ISSUE(buf, k0, ncc)                                              \
    {                                                                            \
        cp16(&Vs[buf][vk0 * 136 + vc0],                                          \
             g_v + vrow0 + (size_t)((k0) + vk0) * vstride + (ncc) + vc0);        \
        cp16(&Vs[buf][vk1 * 136 + vc1],                                          \
             g_v + vrow0 + (size_t)((k0) + vk1) * vstride + (ncc) + vc1);        \
        cp_commit();                                                             \
    }

    for (int nc = 0; nc < NC; nc += 128) {
        float acc[3][4][4] = {};

        PVV_ISSUE(0, 0, nc);
        int cur = 0;
        for (int k0 = 0; k0 < 96; k0 += 16) {
            if (k0 + 16 < 96) { PVV_ISSUE(cur ^ 1, k0 + 16, nc); cp_wait<1>(); }
            else              { cp_wait<0>(); }
            __syncthreads();   // Vs[cur] ready for all; Ps done on first pass

            const float* Vsc = Vs[cur];
            #pragma unroll
            for (int kc = 0; kc < 16; kc += 8) {
                unsigned a[3][4], b[4][2];
                #pragma unroll
                for (int i = 0; i < 3; i++) {
                    int mb = wm * 48 + i * 16;
                    a[i][0] = __float_as_uint(Ps[(mb + g)     * 100 + k0 + kc + t]);
                    a[i][1] = __float_as_uint(Ps[(mb + g + 8) * 100 + k0 + kc + t]);
                    a[i][2] = __float_as_uint(Ps[(mb + g)     * 100 + k0 + kc + t + 4]);
                    a[i][3] = __float_as_uint(Ps[(mb + g + 8) * 100 + k0 + kc + t + 4]);
                }
                #pragma unroll
                for (int j = 0; j < 4; j++) {
                    int nb = wn * 32 + j * 8;
                    b[j][0] = __float_as_uint(Vsc[(kc + t)     * 136 + nb + g]);
                    b[j][1] = __float_as_uint(Vsc[(kc + t + 4) * 136 + nb + g]);
                }
                #pragma unroll
                for (int i = 0; i < 3; i++)
                    #pragma unroll
                    for (int j = 0; j < 4; j++)
                        mma_tf32(acc[i][j], a[i], b[j]);
            }
            __syncthreads();   // all warps done with Vs[cur] before refill
            cur ^= 1;
        }

        // Epilogue for this n-chunk
        #pragma unroll
        for (int i = 0; i < 3; i++) {
            int r0 = wm * 48 + i * 16 + g;
            #pragma unroll
            for (int j = 0; j < 4; j++) {
                int col = nc + wn * 32 + j * 8 + 2 * t;
                size_t o0 = vrow0 + (size_t)r0 * vstride + col;
                size_t o1 = vrow0 + (size_t)(r0 + 8) * vstride + col;
                if (mode == 0) {
                    *(float2*)(g_yv + o0) = make_float2(acc[i][j][0], acc[i][j][1]);
                    *(float2*)(g_yv + o1) = make_float2(acc[i][j][2], acc[i][j][3]);
                } else {
                    float2 yv0 = *(const float2*)(g_yv + o0);
                    float2 yv1 = *(const float2*)(g_yv + o1);
                    float2 x0  = *(const float2*)(x + o0);
                    float2 x1  = *(const float2*)(x + o1);
                    *(float2*)(out + o0) = make_float2(x0.x + gam * (yv0.x + acc[i][j][0]),
                                                       x0.y + gam * (yv0.y + acc[i][j][1]));
                    *(float2*)(out + o1) = make_float2(x1.x + gam * (yv1.x + acc[i][j][2]),
                                                       x1.y + gam * (yv1.y + acc[i][j][3]));
                }
            }
        }
    }
    #undef PVV_ISSUE
}

// =========================================================================
extern "C" void kernel_launch(void* const* d_in, const int* in_sizes, int n_in,
                              void* d_out, int out_size)
{
    const float* x     = (const float*)d_in[0];
    const float* Wq    = (const float*)d_in[1];
    const float* bq    = (const float*)d_in[2];
    const float* Wk    = (const float*)d_in[3];
    const float* bk    = (const float*)d_in[4];
    const float* Wv    = (const float*)d_in[5];
    const float* bv    = (const float*)d_in[6];
    const float* gamma = (const float*)d_in[7];
    float* out = (float*)d_out;
    (void)in_sizes; (void)n_in; (void)out_size;

    // Projections (tensor cores, tf32, cp.async pipelined)
    proj_kernel<<<dim3(1, 576), 256>>>(x, Wq, Wk, bq, bk, 0);           // q | k
    proj_kernel<<<dim3(4, 576), 256>>>(x, Wv, nullptr, bv, nullptr, 1); // v

    // Logits (scalar fp32 — feeds softmax, highest sensitivity)
    logits_kernel<<<NB * NW, 256>>>(0);
    logits_kernel<<<NB * NH, 256>>>(1);

    // Joint softmax (writes tf32-rounded probs)
    softmax_kernel<<<NT / 8, 256>>>();

    // Attention-value (tf32 mma, cp.async pipelined) + epilogue
    pv_kernel<<<NB * NW, 256>>>(x, gamma, out, 0);
    pv_kernel<<<NB * NH, 256>>>(x, gamma, out, 1);
}

// round 8
// speedup vs baseline: 2.9558x; 1.0724x over previous
#include <cuda_runtime.h>
#include <cstddef>

#define NB 8
#define NH 96
#define NW 96
#define NC 512
#define NCQ 64
#define NT (NB*NH*NW)   // 73728 tokens

typedef unsigned long long u64;

// ---------------- scratch (device globals; no runtime allocation) --------
__device__ float g_q[(size_t)NT*NCQ];          // [t][64]
__device__ float g_k[(size_t)NT*NCQ];          // [t][64]
__device__ float g_v[(size_t)NT*NC];           // [t][512] (tf32-rounded)
__device__ float g_sv[(size_t)NB*NW*NH*NH];    // [b][w][h][g] logits/probs
__device__ float g_sh[(size_t)NT*NW];          // [b][h][w][u] logits/probs
__device__ float g_yv[(size_t)NT*NC];          // [t][512]

// ---------------- helpers ------------------------------------------------
__device__ __forceinline__ float to_tf32(float x) {
    unsigned u; asm("cvt.rna.tf32.f32 %0, %1;" : "=r"(u) : "f"(x));
    return __uint_as_float(u);
}
__device__ __forceinline__ void mma_tf32(float (&c)[4], const unsigned (&a)[4],
                                         const unsigned (&b)[2]) {
    asm volatile(
        "mma.sync.aligned.m16n8k8.row.col.f32.tf32.tf32.f32 "
        "{%0,%1,%2,%3}, {%4,%5,%6,%7}, {%8,%9}, {%0,%1,%2,%3};\n"
        : "+f"(c[0]), "+f"(c[1]), "+f"(c[2]), "+f"(c[3])
        : "r"(a[0]), "r"(a[1]), "r"(a[2]), "r"(a[3]),
          "r"(b[0]), "r"(b[1]));
}
__device__ __forceinline__ void cp16(void* s, const void* g) {
    unsigned sa = (unsigned)__cvta_generic_to_shared(s);
    asm volatile("cp.async.ca.shared.global [%0], [%1], 16;" :: "r"(sa), "l"(g));
}
__device__ __forceinline__ void cp_commit() {
    asm volatile("cp.async.commit_group;");
}
template<int N> __device__ __forceinline__ void cp_wait() {
    asm volatile("cp.async.wait_group %0;" :: "n"(N));
}

// =========================================================================
// Projection GEMM via tf32 mma, cp.async double-buffered.
// C = A(M,512) @ B(512,N) + bias.  BM=128, BN=128, BK=16, 256 thr,
// warp grid 4m x 2n (warp tile 32x64).
// mode 0: B = [Wq | Wk] (N=128) -> g_q / g_k (fp32)
// mode 1: B = Wv chunk (blockIdx.x*128) -> g_v (tf32-rounded)
// grid = (n_chunks, m_tiles) so same-A blocks share a wave (L2 reuse).
// =========================================================================
__global__ __launch_bounds__(256) void proj_kernel(
    const float* __restrict__ A, const float* __restrict__ B0,
    const float* __restrict__ B1, const float* __restrict__ bias0,
    const float* __restrict__ bias1, int mode)
{
    __shared__ float As[2][128 * 20];
    __shared__ float Bs[2][16 * 136];

    const int tid  = threadIdx.x;
    const int lane = tid & 31, wid = tid >> 5;
    const int wm = wid & 3, wn = wid >> 2;   // 4 x 2 warps
    const int g = lane >> 2, t = lane & 3;
    const size_t bm = (size_t)blockIdx.y * 128;
    const int bn = (mode == 1) ? blockIdx.x * 128 : 0;

    const int am0 = tid >> 2,         ac0 = (tid & 3) * 4;
    const int am1 = (tid + 256) >> 2, ac1 = ((tid + 256) & 3) * 4;
    const int bk0 = tid >> 5,         bc0 = (tid & 31) * 4;
    const int bk1 = (tid + 256) >> 5, bc1 = ((tid + 256) & 31) * 4;

    #define PROJ_ISSUE(buf, k0)                                                  \
    {                                                                            \
        cp16(&As[buf][am0 * 20 + ac0], A + (bm + am0) * 512 + (k0) + ac0);       \
        cp16(&As[buf][am1 * 20 + ac1], A + (bm + am1) * 512 + (k0) + ac1);       \
        const float* s0, *s1;                                                    \
        if (mode == 0) {                                                         \
            s0 = (bc0 < 64) ? (B0 + (size_t)((k0) + bk0) * 64 + bc0)             \
                            : (B1 + (size_t)((k0) + bk0) * 64 + bc0 - 64);       \
            s1 = (bc1 < 64) ? (B0 + (size_t)((k0) + bk1) * 64 + bc1)             \
                            : (B1 + (size_t)((k0) + bk1) * 64 + bc1 - 64);       \
        } else {                                                                 \
            s0 = B0 + (size_t)((k0) + bk0) * 512 + bn + bc0;                     \
            s1 = B0 + (size_t)((k0) + bk1) * 512 + bn + bc1;                     \
        }                                                                        \
        cp16(&Bs[buf][bk0 * 136 + bc0], s0);                                     \
        cp16(&Bs[buf][bk1 * 136 + bc1], s1);                                     \
        cp_commit();                                                             \
    }

    float acc[2][8][4] = {};

    PROJ_ISSUE(0, 0);
    int cur = 0;
    for (int k0 = 0; k0 < 512; k0 += 16) {
        if (k0 + 16 < 512) { PROJ_ISSUE(cur ^ 1, k0 + 16); cp_wait<1>(); }
        else               { cp_wait<0>(); }
        __syncthreads();

        const float* Asc = As[cur];
        const float* Bsc = Bs[cur];
        #pragma unroll
        for (int kc = 0; kc < 16; kc += 8) {
            unsigned a[2][4], b[8][2];
            #pragma unroll
            for (int i = 0; i < 2; i++) {
                int mb = wm * 32 + i * 16;
                a[i][0] = __float_as_uint(Asc[(mb + g)     * 20 + kc + t]);
                a[i][1] = __float_as_uint(Asc[(mb + g + 8) * 20 + kc + t]);
                a[i][2] = __float_as_uint(Asc[(mb + g)     * 20 + kc + t + 4]);
                a[i][3] = __float_as_uint(Asc[(mb + g + 8) * 20 + kc + t + 4]);
            }
            #pragma unroll
            for (int j = 0; j < 8; j++) {
                int nb = wn * 64 + j * 8;
                b[j][0] = __float_as_uint(Bsc[(kc + t)     * 136 + nb + g]);
                b[j][1] = __float_as_uint(Bsc[(kc + t + 4) * 136 + nb + g]);
            }
            #pragma unroll
            for (int i = 0; i < 2; i++)
                #pragma unroll
                for (int j = 0; j < 8; j++)
                    mma_tf32(acc[i][j], a[i], b[j]);
        }
        __syncthreads();
        cur ^= 1;
    }
    #undef PROJ_ISSUE

    // Epilogue: c0,c1 at (row, 2t..2t+1); c2,c3 at (row+8)
    #pragma unroll
    for (int i = 0; i < 2; i++) {
        size_t r0 = bm + wm * 32 + i * 16 + g;
        #pragma unroll
        for (int j = 0; j < 8; j++) {
            int n = wn * 64 + j * 8 + 2 * t;   // block-local col
            if (mode == 0) {
                const float* bp = (wn == 0) ? bias0 : bias1;
                int nn = (wn == 0) ? n : (n - 64);
                float b0v = bp[nn], b1v = bp[nn + 1];
                float* dst = (wn == 0) ? g_q : g_k;
                *(float2*)(dst + r0 * 64 + nn)       = make_float2(acc[i][j][0] + b0v, acc[i][j][1] + b1v);
                *(float2*)(dst + (r0 + 8) * 64 + nn) = make_float2(acc[i][j][2] + b0v, acc[i][j][3] + b1v);
            } else {
                int gc = bn + n;
                float b0v = bias0[gc], b1v = bias0[gc + 1];
                *(float2*)(g_v + r0 * 512 + gc)       = make_float2(to_tf32(acc[i][j][0] + b0v), to_tf32(acc[i][j][1] + b1v));
                *(float2*)(g_v + (r0 + 8) * 512 + gc) = make_float2(to_tf32(acc[i][j][2] + b0v), to_tf32(acc[i][j][3] + b1v));
            }
        }
    }
}

// =========================================================================
// Logits via 3xTF32 split mma (~fp32 accuracy on tensor pipe):
// v = hi + lo, hi = tf32(v), lo = tf32(v - hi);
// S = Qhi Khi^T + Qhi Klo^T + Qlo Khi^T.
// S[96][96] = Q(96x64) @ K(96x64)^T; 8 warps 2m x 4n, warp tile 48x24.
// mode 0: vertical (per (b,w), strided, diag masked) -> g_sv
// mode 1: horizontal (per (b,h), contiguous)         -> g_sh
// =========================================================================
__global__ __launch_bounds__(256) void logits_kernel(int mode)
{
    __shared__ float Qs[96 * 68];
    __shared__ float Ks[96 * 68];

    const int tid  = threadIdx.x;
    const int lane = tid & 31, wid = tid >> 5;
    const int wm = wid & 1, wn = wid >> 1;   // 2 x 4
    const int g = lane >> 2, t = lane & 3;
    const int bid = blockIdx.x;

    size_t base; int stride;
    if (mode == 0) {
        int b = bid / NW, w = bid % NW;
        base = ((size_t)b * NH * NW + w) * NCQ;
        stride = NW * NCQ;
    } else {
        base = (size_t)bid * NW * NCQ;
        stride = NCQ;
    }
    float* __restrict__ out = (mode == 0 ? g_sv : g_sh) + (size_t)bid * 96 * 96;

    #pragma unroll
    for (int it = 0; it < 6; it++) {
        int idx = tid + it * 256;              // 0..1535 ; 96 rows x 16 float4
        int r = idx >> 4, c4 = (idx & 15) * 4;
        *(float4*)&Qs[r * 68 + c4] = *(const float4*)(g_q + base + (size_t)r * stride + c4);
        *(float4*)&Ks[r * 68 + c4] = *(const float4*)(g_k + base + (size_t)r * stride + c4);
    }
    __syncthreads();

    float acc[3][3][4] = {};
    #pragma unroll
    for (int kc = 0; kc < 64; kc += 8) {
        unsigned ah[3][4], al[3][4], bh[3][2], bl[3][2];
        #pragma unroll
        for (int i = 0; i < 3; i++) {
            int mb = wm * 48 + i * 16;
            float f0 = Qs[(mb + g)     * 68 + kc + t];
            float f1 = Qs[(mb + g + 8) * 68 + kc + t];
            float f2 = Qs[(mb + g)     * 68 + kc + t + 4];
            float f3 = Qs[(mb + g + 8) * 68 + kc + t + 4];
            float h0 = to_tf32(f0), h1 = to_tf32(f1), h2 = to_tf32(f2), h3 = to_tf32(f3);
            ah[i][0] = __float_as_uint(h0); al[i][0] = __float_as_uint(to_tf32(f0 - h0));
            ah[i][1] = __float_as_uint(h1); al[i][1] = __float_as_uint(to_tf32(f1 - h1));
            ah[i][2] = __float_as_uint(h2); al[i][2] = __float_as_uint(to_tf32(f2 - h2));
            ah[i][3] = __float_as_uint(h3); al[i][3] = __float_as_uint(to_tf32(f3 - h3));
        }
        #pragma unroll
        for (int j = 0; j < 3; j++) {
            int nb = wn * 24 + j * 8;
            float f0 = Ks[(nb + g) * 68 + kc + t];
            float f1 = Ks[(nb + g) * 68 + kc + t + 4];
            float h0 = to_tf32(f0), h1 = to_tf32(f1);
            bh[j][0] = __float_as_uint(h0); bl[j][0] = __float_as_uint(to_tf32(f0 - h0));
            bh[j][1] = __float_as_uint(h1); bl[j][1] = __float_as_uint(to_tf32(f1 - h1));
        }
        #pragma unroll
        for (int i = 0; i < 3; i++)
            #pragma unroll
            for (int j = 0; j < 3; j++) {
                mma_tf32(acc[i][j], ah[i], bl[j]);   // hi*lo
                mma_tf32(acc[i][j], al[i], bh[j]);   // lo*hi
                mma_tf32(acc[i][j], ah[i], bh[j]);   // hi*hi (last: largest term)
            }
    }

    #pragma unroll
    for (int i = 0; i < 3; i++) {
        int r = wm * 48 + i * 16 + g;
        #pragma unroll
        for (int j = 0; j < 3; j++) {
            int c = wn * 24 + j * 8 + 2 * t;
            float v0 = acc[i][j][0], v1 = acc[i][j][1];
            float v2 = acc[i][j][2], v3 = acc[i][j][3];
            if (mode == 0) {
                if (r == c)         v0 = -1e30f;
                if (r == c + 1)     v1 = -1e30f;
                if (r + 8 == c)     v2 = -1e30f;
                if (r + 8 == c + 1) v3 = -1e30f;
            }
            *(float2*)(out + r * 96 + c)       = make_float2(v0, v1);
            *(float2*)(out + (r + 8) * 96 + c) = make_float2(v2, v3);
        }
    }
}

// =========================================================================
// Softmax over 192 concatenated logits per token; writes tf32-rounded probs.
// =========================================================================
__global__ void softmax_kernel()
{
    int gw = (int)((blockIdx.x * blockDim.x + threadIdx.x) >> 5);
    int lane = threadIdx.x & 31;
    if (gw >= NT) return;
    int b = gw / (NH * NW), rem = gw % (NH * NW);
    int h = rem / NW, w = rem % NW;

    float* __restrict__ svp = g_sv + (((size_t)b * NW + w) * NH + h) * NH;
    float* __restrict__ shp = g_sh + (size_t)gw * NW;

    float v[6];
    float m = -3.4e38f;
    #pragma unroll
    for (int i = 0; i < 3; i++) { v[i]     = svp[lane + 32 * i]; m = fmaxf(m, v[i]); }
    #pragma unroll
    for (int i = 0; i < 3; i++) { v[3 + i] = shp[lane + 32 * i]; m = fmaxf(m, v[3 + i]); }
    #pragma unroll
    for (int o = 16; o; o >>= 1) m = fmaxf(m, __shfl_xor_sync(0xffffffffu, m, o));

    float s = 0.f;
    #pragma unroll
    for (int i = 0; i < 6; i++) { v[i] = __expf(v[i] - m); s += v[i]; }
    #pragma unroll
    for (int o = 16; o; o >>= 1) s += __shfl_xor_sync(0xffffffffu, s, o);
    float inv = 1.0f / s;

    #pragma unroll
    for (int i = 0; i < 3; i++) svp[lane + 32 * i] = to_tf32(v[i] * inv);
    #pragma unroll
    for (int i = 0; i < 3; i++) shp[lane + 32 * i] = to_tf32(v[3 + i] * inv);
}

// =========================================================================
// PV via tf32 mma, cp.async double-buffered V tiles.
// Y(96x512) = P(96x96) @ V(96x512); P loaded once per block,
// 4 internal n-chunks of 128. 256 thr; warp grid 2m x 4n (48x32).
// mode 0: vertical   (P=av per (b,w), V rows strided)  -> g_yv
// mode 1: horizontal (P=ah per (b,h), V rows contig)   -> out = x + gam*(yv+yh)
// =========================================================================
__global__ __launch_bounds__(256) void pv_kernel(
    const float* __restrict__ x, const float* __restrict__ gamma_p,
    float* __restrict__ out, int mode)
{
    __shared__ float Ps[96 * 100];      // 38,400 B
    __shared__ float Vs[2][16 * 136];   // 2 x 8,704 B

    const int tid  = threadIdx.x;
    const int lane = tid & 31, wid = tid >> 5;
    const int wm = wid & 1, wn = wid >> 1;   // 2 x 4 warps
    const int g = lane >> 2, t = lane & 3;
    const int bid = blockIdx.x;

    const float* __restrict__ Pb = (mode == 0 ? g_sv : g_sh) + (size_t)bid * 96 * 96;
    size_t vrow0; int vstride;
    if (mode == 0) {
        int b = bid / NW, w = bid % NW;
        vrow0 = ((size_t)b * NH * NW + w) * NC;
        vstride = NW * NC;
    } else {
        vrow0 = (size_t)bid * NW * NC;
        vstride = NC;
    }

    // load P once (96x96 = 2304 float4, 9/thread); probs already tf32-rounded
    #pragma unroll
    for (int it = 0; it < 9; it++) {
        int idx = tid + it * 256;
        int m = idx / 24, c = idx % 24;
        *(float4*)&Ps[m * 100 + c * 4] = *(const float4*)(Pb + m * 96 + c * 4);
    }
    float gam = (mode == 1) ? *gamma_p : 0.f;

    // V tile: 16 rows x 128 cols = 512 float4, 2/thread
    const int vk0 = tid >> 5,         vc0 = (tid & 31) * 4;
    const int vk1 = (tid + 256) >> 5, vc1 = ((tid + 256) & 31) * 4;

    #define PVV_ISSUE(buf, k0, ncc)                                              \
    {                                                                            \
        cp16(&Vs[buf][vk0 * 136 + vc0],                                          \
             g_v + vrow0 + (size_t)((k0) + vk0) * vstride + (ncc) + vc0);        \
        cp16(&Vs[buf][vk1 * 136 + vc1],                                          \
             g_v + vrow0 + (size_t)((k0) + vk1) * vstride + (ncc) + vc1);        \
        cp_commit();                                                             \
    }

    for (int nc = 0; nc < NC; nc += 128) {
        float acc[3][4][4] = {};

        PVV_ISSUE(0, 0, nc);
        int cur = 0;
        for (int k0 = 0; k0 < 96; k0 += 16) {
            if (k0 + 16 < 96) { PVV_ISSUE(cur ^ 1, k0 + 16, nc); cp_wait<1>(); }
            else              { cp_wait<0>(); }
            __syncthreads();   // Vs[cur] ready for all; Ps done on first pass

            const float* Vsc = Vs[cur];
            #pragma unroll
            for (int kc = 0; kc < 16; kc += 8) {
                unsigned a[3][4], b[4][2];
                #pragma unroll
                for (int i = 0; i < 3; i++) {
                    int mb = wm * 48 + i * 16;
                    a[i][0] = __float_as_uint(Ps[(mb + g)     * 100 + k0 + kc + t]);
                    a[i][1] = __float_as_uint(Ps[(mb + g + 8) * 100 + k0 + kc + t]);
                    a[i][2] = __float_as_uint(Ps[(mb + g)     * 100 + k0 + kc + t + 4]);
                    a[i][3] = __float_as_uint(Ps[(mb + g + 8) * 100 + k0 + kc + t + 4]);
                }
                #pragma unroll
                for (int j = 0; j < 4; j++) {
                    int nb = wn * 32 + j * 8;
                    b[j][0] = __float_as_uint(Vsc[(kc + t)     * 136 + nb + g]);
                    b[j][1] = __float_as_uint(Vsc[(kc + t + 4) * 136 + nb + g]);
                }
                #pragma unroll
                for (int i = 0; i < 3; i++)
                    #pragma unroll
                    for (int j = 0; j < 4; j++)
                        mma_tf32(acc[i][j], a[i], b[j]);
            }
            __syncthreads();   // all warps done with Vs[cur] before refill
            cur ^= 1;
        }

        // Epilogue for this n-chunk
        #pragma unroll
        for (int i = 0; i < 3; i++) {
            int r0 = wm * 48 + i * 16 + g;
            #pragma unroll
            for (int j = 0; j < 4; j++) {
                int col = nc + wn * 32 + j * 8 + 2 * t;
                size_t o0 = vrow0 + (size_t)r0 * vstride + col;
                size_t o1 = vrow0 + (size_t)(r0 + 8) * vstride + col;
                if (mode == 0) {
                    *(float2*)(g_yv + o0) = make_float2(acc[i][j][0], acc[i][j][1]);
                    *(float2*)(g_yv + o1) = make_float2(acc[i][j][2], acc[i][j][3]);
                } else {
                    float2 yv0 = *(const float2*)(g_yv + o0);
                    float2 yv1 = *(const float2*)(g_yv + o1);
                    float2 x0  = *(const float2*)(x + o0);
                    float2 x1  = *(const float2*)(x + o1);
                    *(float2*)(out + o0) = make_float2(x0.x + gam * (yv0.x + acc[i][j][0]),
                                                       x0.y + gam * (yv0.y + acc[i][j][1]));
                    *(float2*)(out + o1) = make_float2(x1.x + gam * (yv1.x + acc[i][j][2]),
                                                       x1.y + gam * (yv1.y + acc[i][j][3]));
                }
            }
        }
    }
    #undef PVV_ISSUE
}

// =========================================================================
extern "C" void kernel_launch(void* const* d_in, const int* in_sizes, int n_in,
                              void* d_out, int out_size)
{
    const float* x     = (const float*)d_in[0];
    const float* Wq    = (const float*)d_in[1];
    const float* bq    = (const float*)d_in[2];
    const float* Wk    = (const float*)d_in[3];
    const float* bk    = (const float*)d_in[4];
    const float* Wv    = (const float*)d_in[5];
    const float* bv    = (const float*)d_in[6];
    const float* gamma = (const float*)d_in[7];
    float* out = (float*)d_out;
    (void)in_sizes; (void)n_in; (void)out_size;

    // Projections (tensor cores, tf32, cp.async pipelined)
    proj_kernel<<<dim3(1, 576), 256>>>(x, Wq, Wk, bq, bk, 0);           // q | k
    proj_kernel<<<dim3(4, 576), 256>>>(x, Wv, nullptr, bv, nullptr, 1); // v

    // Logits (3xTF32 split mma — ~fp32 accuracy on tensor pipe)
    logits_kernel<<<NB * NW, 256>>>(0);
    logits_kernel<<<NB * NH, 256>>>(1);

    // Joint softmax (writes tf32-rounded probs)
    softmax_kernel<<<NT / 8, 256>>>();

    // Attention-value (tf32 mma, cp.async pipelined) + epilogue
    pv_kernel<<<NB * NW, 256>>>(x, gamma, out, 0);
    pv_kernel<<<NB * NH, 256>>>(x, gamma, out, 1);
}

// round 10
// speedup vs baseline: 3.1292x; 1.0587x over previous
#include <cuda_runtime.h>
#include <cuda_bf16.h>
#include <cstddef>

#define NB 8
#define NH 96
#define NW 96
#define NC 512
#define NCQ 64
#define NT (NB*NH*NW)   // 73728 tokens

typedef unsigned long long u64;

// ---------------- scratch (device globals; no runtime allocation) --------
__device__ float g_q[(size_t)NT*NCQ];            // [t][64]
__device__ float g_k[(size_t)NT*NCQ];            // [t][64]
__device__ float g_v[(size_t)NT*NC];             // [t][512] (tf32-rounded)
__device__ float g_sv[(size_t)NB*NW*NH*NH];      // [b][w][h][g] logits/probs
__device__ float g_sh[(size_t)NT*NW];            // [b][h][w][u] logits/probs
__device__ __nv_bfloat16 g_yv[(size_t)NT*NC];    // [t][512] bf16 (residual path)

// ---------------- helpers ------------------------------------------------
__device__ __forceinline__ float to_tf32(float x) {
    unsigned u; asm("cvt.rna.tf32.f32 %0, %1;" : "=r"(u) : "f"(x));
    return __uint_as_float(u);
}
__device__ __forceinline__ void mma_tf32(float (&c)[4], const unsigned (&a)[4],
                                         const unsigned (&b)[2]) {
    asm volatile(
        "mma.sync.aligned.m16n8k8.row.col.f32.tf32.tf32.f32 "
        "{%0,%1,%2,%3}, {%4,%5,%6,%7}, {%8,%9}, {%0,%1,%2,%3};\n"
        : "+f"(c[0]), "+f"(c[1]), "+f"(c[2]), "+f"(c[3])
        : "r"(a[0]), "r"(a[1]), "r"(a[2]), "r"(a[3]),
          "r"(b[0]), "r"(b[1]));
}
__device__ __forceinline__ void cp16(void* s, const void* g) {
    unsigned sa = (unsigned)__cvta_generic_to_shared(s);
    asm volatile("cp.async.ca.shared.global [%0], [%1], 16;" :: "r"(sa), "l"(g));
}
__device__ __forceinline__ void cp_commit() {
    asm volatile("cp.async.commit_group;");
}
template<int N> __device__ __forceinline__ void cp_wait() {
    asm volatile("cp.async.wait_group %0;" :: "n"(N));
}

// =========================================================================
// Merged projection GEMM via tf32 mma, cp.async double-buffered.
// grid (5, 576): blockIdx.x = 0..3 -> v chunk (B = Wv cols bn..bn+127,
// output g_v tf32-rounded); blockIdx.x = 4 -> q|k (B = [Wq|Wk], N=128,
// outputs g_q / g_k fp32).  BM=128, BK=16, 256 thr, warp grid 4m x 2n.
// All 5 same-row blocks share the A tile through L2 (one x read total).
// =========================================================================
__global__ __launch_bounds__(256) void proj_kernel(
    const float* __restrict__ A,  const float* __restrict__ Wq,
    const float* __restrict__ Wk, const float* __restrict__ Wv,
    const float* __restrict__ bq, const float* __restrict__ bk,
    const float* __restrict__ bv)
{
    __shared__ float As[2][128 * 20];
    __shared__ float Bs[2][16 * 136];

    const int tid  = threadIdx.x;
    const int lane = tid & 31, wid = tid >> 5;
    const int wm = wid & 3, wn = wid >> 2;   // 4 x 2 warps, warp tile 32x64
    const int g = lane >> 2, t = lane & 3;
    const size_t bm = (size_t)blockIdx.y * 128;
    const int vmode = (blockIdx.x < 4);
    const int bn = vmode ? blockIdx.x * 128 : 0;

    const int am0 = tid >> 2,         ac0 = (tid & 3) * 4;
    const int am1 = (tid + 256) >> 2, ac1 = ((tid + 256) & 3) * 4;
    const int bk0 = tid >> 5,         bc0 = (tid & 31) * 4;
    const int bk1 = (tid + 256) >> 5, bc1 = ((tid + 256) & 31) * 4;

    #define PROJ_ISSUE(buf, k0)                                                  \
    {                                                                            \
        cp16(&As[buf][am0 * 20 + ac0], A + (bm + am0) * 512 + (k0) + ac0);       \
        cp16(&As[buf][am1 * 20 + ac1], A + (bm + am1) * 512 + (k0) + ac1);       \
        const float* s0, *s1;                                                    \
        if (vmode) {                                                             \
            s0 = Wv + (size_t)((k0) + bk0) * 512 + bn + bc0;                     \
            s1 = Wv + (size_t)((k0) + bk1) * 512 + bn + bc1;                     \
        } else {                                                                 \
            s0 = (bc0 < 64) ? (Wq + (size_t)((k0) + bk0) * 64 + bc0)             \
                            : (Wk + (size_t)((k0) + bk0) * 64 + bc0 - 64);       \
            s1 = (bc1 < 64) ? (Wq + (size_t)((k0) + bk1) * 64 + bc1)             \
                            : (Wk + (size_t)((k0) + bk1) * 64 + bc1 - 64);       \
        }                                                                        \
        cp16(&Bs[buf][bk0 * 136 + bc0], s0);                                     \
        cp16(&Bs[buf][bk1 * 136 + bc1], s1);                                     \
        cp_commit();                                                             \
    }

    float acc[2][8][4] = {};

    PROJ_ISSUE(0, 0);
    int cur = 0;
    for (int k0 = 0; k0 < 512; k0 += 16) {
        if (k0 + 16 < 512) { PROJ_ISSUE(cur ^ 1, k0 + 16); cp_wait<1>(); }
        else               { cp_wait<0>(); }
        __syncthreads();

        const float* Asc = As[cur];
        const float* Bsc = Bs[cur];
        #pragma unroll
        for (int kc = 0; kc < 16; kc += 8) {
            unsigned a[2][4], b[8][2];
            #pragma unroll
            for (int i = 0; i < 2; i++) {
                int mb = wm * 32 + i * 16;
                a[i][0] = __float_as_uint(Asc[(mb + g)     * 20 + kc + t]);
                a[i][1] = __float_as_uint(Asc[(mb + g + 8) * 20 + kc + t]);
                a[i][2] = __float_as_uint(Asc[(mb + g)     * 20 + kc + t + 4]);
                a[i][3] = __float_as_uint(Asc[(mb + g + 8) * 20 + kc + t + 4]);
            }
            #pragma unroll
            for (int j = 0; j < 8; j++) {
                int nb = wn * 64 + j * 8;
                b[j][0] = __float_as_uint(Bsc[(kc + t)     * 136 + nb + g]);
                b[j][1] = __float_as_uint(Bsc[(kc + t + 4) * 136 + nb + g]);
            }
            #pragma unroll
            for (int i = 0; i < 2; i++)
                #pragma unroll
                for (int j = 0; j < 8; j++)
                    mma_tf32(acc[i][j], a[i], b[j]);
        }
        __syncthreads();
        cur ^= 1;
    }
    #undef PROJ_ISSUE

    // Epilogue: c0,c1 at (row, 2t..2t+1); c2,c3 at (row+8)
    #pragma unroll
    for (int i = 0; i < 2; i++) {
        size_t r0 = bm + wm * 32 + i * 16 + g;
        #pragma unroll
        for (int j = 0; j < 8; j++) {
            int n = wn * 64 + j * 8 + 2 * t;   // block-local col
            if (vmode) {
                int gc = bn + n;
                float b0v = bv[gc], b1v = bv[gc + 1];
                *(float2*)(g_v + r0 * 512 + gc)       = make_float2(to_tf32(acc[i][j][0] + b0v), to_tf32(acc[i][j][1] + b1v));
                *(float2*)(g_v + (r0 + 8) * 512 + gc) = make_float2(to_tf32(acc[i][j][2] + b0v), to_tf32(acc[i][j][3] + b1v));
            } else {
                const float* bp = (wn == 0) ? bq : bk;
                int nn = (wn == 0) ? n : (n - 64);
                float b0v = bp[nn], b1v = bp[nn + 1];
                float* dst = (wn == 0) ? g_q : g_k;
                *(float2*)(dst + r0 * 64 + nn)       = make_float2(acc[i][j][0] + b0v, acc[i][j][1] + b1v);
                *(float2*)(dst + (r0 + 8) * 64 + nn) = make_float2(acc[i][j][2] + b0v, acc[i][j][3] + b1v);
            }
        }
    }
}

// =========================================================================
// Logits via 3xTF32 split mma (~fp32 accuracy on tensor pipe).
// Single launch, grid 1536: mode = bid & 1 (0 = vertical, 1 = horizontal),
// tile index = bid >> 1.
// S[96][96] = Q(96x64) @ K(96x64)^T; 8 warps 2m x 4n, warp tile 48x24.
// =========================================================================
__global__ __launch_bounds__(256) void logits_kernel()
{
    __shared__ float Qs[96 * 68];
    __shared__ float Ks[96 * 68];

    const int tid  = threadIdx.x;
    const int lane = tid & 31, wid = tid >> 5;
    const int wm = wid & 1, wn = wid >> 1;   // 2 x 4
    const int g = lane >> 2, t = lane & 3;
    const int mode = blockIdx.x & 1;
    const int bid = blockIdx.x >> 1;

    size_t base; int stride;
    if (mode == 0) {
        int b = bid / NW, w = bid % NW;
        base = ((size_t)b * NH * NW + w) * NCQ;
        stride = NW * NCQ;
    } else {
        base = (size_t)bid * NW * NCQ;
        stride = NCQ;
    }
    float* __restrict__ out = (mode == 0 ? g_sv : g_sh) + (size_t)bid * 96 * 96;

    #pragma unroll
    for (int it = 0; it < 6; it++) {
        int idx = tid + it * 256;              // 0..1535 ; 96 rows x 16 float4
        int r = idx >> 4, c4 = (idx & 15) * 4;
        *(float4*)&Qs[r * 68 + c4] = *(const float4*)(g_q + base + (size_t)r * stride + c4);
        *(float4*)&Ks[r * 68 + c4] = *(const float4*)(g_k + base + (size_t)r * stride + c4);
    }
    __syncthreads();

    float acc[3][3][4] = {};
    #pragma unroll
    for (int kc = 0; kc < 64; kc += 8) {
        unsigned ah[3][4], al[3][4], bh[3][2], bl[3][2];
        #pragma unroll
        for (int i = 0; i < 3; i++) {
            int mb = wm * 48 + i * 16;
            float f0 = Qs[(mb + g)     * 68 + kc + t];
            float f1 = Qs[(mb + g + 8) * 68 + kc + t];
            float f2 = Qs[(mb + g)     * 68 + kc + t + 4];
            float f3 = Qs[(mb + g + 8) * 68 + kc + t + 4];
            float h0 = to_tf32(f0), h1 = to_tf32(f1), h2 = to_tf32(f2), h3 = to_tf32(f3);
            ah[i][0] = __float_as_uint(h0); al[i][0] = __float_as_uint(to_tf32(f0 - h0));
            ah[i][1] = __float_as_uint(h1); al[i][1] = __float_as_uint(to_tf32(f1 - h1));
            ah[i][2] = __float_as_uint(h2); al[i][2] = __float_as_uint(to_tf32(f2 - h2));
            ah[i][3] = __float_as_uint(h3); al[i][3] = __float_as_uint(to_tf32(f3 - h3));
        }
        #pragma unroll
        for (int j = 0; j < 3; j++) {
            int nb = wn * 24 + j * 8;
            float f0 = Ks[(nb + g) * 68 + kc + t];
            float f1 = Ks[(nb + g) * 68 + kc + t + 4];
            float h0 = to_tf32(f0), h1 = to_tf32(f1);
            bh[j][0] = __float_as_uint(h0); bl[j][0] = __float_as_uint(to_tf32(f0 - h0));
            bh[j][1] = __float_as_uint(h1); bl[j][1] = __float_as_uint(to_tf32(f1 - h1));
        }
        #pragma unroll
        for (int i = 0; i < 3; i++)
            #pragma unroll
            for (int j = 0; j < 3; j++) {
                mma_tf32(acc[i][j], ah[i], bl[j]);   // hi*lo
                mma_tf32(acc[i][j], al[i], bh[j]);   // lo*hi
                mma_tf32(acc[i][j], ah[i], bh[j]);   // hi*hi (last: largest term)
            }
    }

    #pragma unroll
    for (int i = 0; i < 3; i++) {
        int r = wm * 48 + i * 16 + g;
        #pragma unroll
        for (int j = 0; j < 3; j++) {
            int c = wn * 24 + j * 8 + 2 * t;
            float v0 = acc[i][j][0], v1 = acc[i][j][1];
            float v2 = acc[i][j][2], v3 = acc[i][j][3];
            if (mode == 0) {
                if (r == c)         v0 = -1e30f;
                if (r == c + 1)     v1 = -1e30f;
                if (r + 8 == c)     v2 = -1e30f;
                if (r + 8 == c + 1) v3 = -1e30f;
            }
            *(float2*)(out + r * 96 + c)       = make_float2(v0, v1);
            *(float2*)(out + (r + 8) * 96 + c) = make_float2(v2, v3);
        }
    }
}

// =========================================================================
// Softmax over 192 concatenated logits per token; writes tf32-rounded probs.
// =========================================================================
__global__ void softmax_kernel()
{
    int gw = (int)((blockIdx.x * blockDim.x + threadIdx.x) >> 5);
    int lane = threadIdx.x & 31;
    if (gw >= NT) return;
    int b = gw / (NH * NW), rem = gw % (NH * NW);
    int h = rem / NW, w = rem % NW;

    float* __restrict__ svp = g_sv + (((size_t)b * NW + w) * NH + h) * NH;
    float* __restrict__ shp = g_sh + (size_t)gw * NW;

    float v[6];
    float m = -3.4e38f;
    #pragma unroll
    for (int i = 0; i < 3; i++) { v[i]     = svp[lane + 32 * i]; m = fmaxf(m, v[i]); }
    #pragma unroll
    for (int i = 0; i < 3; i++) { v[3 + i] = shp[lane + 32 * i]; m = fmaxf(m, v[3 + i]); }
    #pragma unroll
    for (int o = 16; o; o >>= 1) m = fmaxf(m, __shfl_xor_sync(0xffffffffu, m, o));

    float s = 0.f;
    #pragma unroll
    for (int i = 0; i < 6; i++) { v[i] = __expf(v[i] - m); s += v[i]; }
    #pragma unroll
    for (int o = 16; o; o >>= 1) s += __shfl_xor_sync(0xffffffffu, s, o);
    float inv = 1.0f / s;

    #pragma unroll
    for (int i = 0; i < 3; i++) svp[lane + 32 * i] = to_tf32(v[i] * inv);
    #pragma unroll
    for (int i = 0; i < 3; i++) shp[lane + 32 * i] = to_tf32(v[3 + i] * inv);
}

// =========================================================================
// PV via tf32 mma, cp.async double-buffered V tiles.
// Y(96x512) = P(96x96) @ V(96x512); P loaded once per block,
// 4 internal n-chunks of 128. 256 thr; warp grid 2m x 4n (48x32).
// mode 0: vertical   (P=av per (b,w), V rows strided)  -> g_yv (bf16)
// mode 1: horizontal (P=ah per (b,h), V rows contig)   -> out = x + gam*(yv+yh)
// =========================================================================
__global__ __launch_bounds__(256) void pv_kernel(
    const float* __restrict__ x, const float* __restrict__ gamma_p,
    float* __restrict__ out, int mode)
{
    __shared__ float Ps[96 * 100];      // 38,400 B
    __shared__ float Vs[2][16 * 136];   // 2 x 8,704 B

    const int tid  = threadIdx.x;
    const int lane = tid & 31, wid = tid >> 5;
    const int wm = wid & 1, wn = wid >> 1;   // 2 x 4 warps
    const int g = lane >> 2, t = lane & 3;
    const int bid = blockIdx.x;

    const float* __restrict__ Pb = (mode == 0 ? g_sv : g_sh) + (size_t)bid * 96 * 96;
    size_t vrow0; int vstride;
    if (mode == 0) {
        int b = bid / NW, w = bid % NW;
        vrow0 = ((size_t)b * NH * NW + w) * NC;
        vstride = NW * NC;
    } else {
        vrow0 = (size_t)bid * NW * NC;
        vstride = NC;
    }

    // load P once (96x96 = 2304 float4, 9/thread); probs already tf32-rounded
    #pragma unroll
    for (int it = 0; it < 9; it++) {
        int idx = tid + it * 256;
        int m = idx / 24, c = idx % 24;
        *(float4*)&Ps[m * 100 + c * 4] = *(const float4*)(Pb + m * 96 + c * 4);
    }
    float gam = (mode == 1) ? *gamma_p : 0.f;

    // V tile: 16 rows x 128 cols = 512 float4, 2/thread
    const int vk0 = tid >> 5,         vc0 = (tid & 31) * 4;
    const int vk1 = (tid + 256) >> 5, vc1 = ((tid + 256) & 31) * 4;

    #define PVV_ISSUE(buf, k0, ncc)                                              \
    {                                                                            \
        cp16(&Vs[buf][vk0 * 136 + vc0],                                          \
             g_v + vrow0 + (size_t)((k0) + vk0) * vstride + (ncc) + vc0);        \
        cp16(&Vs[buf][vk1 * 136 + vc1],                                          \
             g_v + vrow0 + (size_t)((k0) + vk1) * vstride + (ncc) + vc1);        \
        cp_commit();                                                             \
    }

    for (int nc = 0; nc < NC; nc += 128) {
        float acc[3][4][4] = {};

        PVV_ISSUE(0, 0, nc);
        int cur = 0;
        for (int k0 = 0; k0 < 96; k0 += 16) {
            if (k0 + 16 < 96) { PVV_ISSUE(cur ^ 1, k0 + 16, nc); cp_wait<1>(); }
            else              { cp_wait<0>(); }
            __syncthreads();   // Vs[cur] ready for all; Ps done on first pass

            const float* Vsc = Vs[cur];
            #pragma unroll
            for (int kc = 0; kc < 16; kc += 8) {
                unsigned a[3][4], b[4][2];
                #pragma unroll
                for (int i = 0; i < 3; i++) {
                    int mb = wm * 48 + i * 16;
                    a[i][0] = __float_as_uint(Ps[(mb + g)     * 100 + k0 + kc + t]);
                    a[i][1] = __float_as_uint(Ps[(mb + g + 8) * 100 + k0 + kc + t]);
                    a[i][2] = __float_as_uint(Ps[(mb + g)     * 100 + k0 + kc + t + 4]);
                    a[i][3] = __float_as_uint(Ps[(mb + g + 8) * 100 + k0 + kc + t + 4]);
                }
                #pragma unroll
                for (int j = 0; j < 4; j++) {
                    int nb = wn * 32 + j * 8;
                    b[j][0] = __float_as_uint(Vsc[(kc + t)     * 136 + nb + g]);
                    b[j][1] = __float_as_uint(Vsc[(kc + t + 4) * 136 + nb + g]);
                }
                #pragma unroll
                for (int i = 0; i < 3; i++)
                    #pragma unroll
                    for (int j = 0; j < 4; j++)
                        mma_tf32(acc[i][j], a[i], b[j]);
            }
            __syncthreads();   // all warps done with Vs[cur] before refill
            cur ^= 1;
        }

        // Epilogue for this n-chunk
        #pragma unroll
        for (int i = 0; i < 3; i++) {
            int r0 = wm * 48 + i * 16 + g;
            #pragma unroll
            for (int j = 0; j < 4; j++) {
                int col = nc + wn * 32 + j * 8 + 2 * t;
                size_t o0 = vrow0 + (size_t)r0 * vstride + col;
                size_t o1 = vrow0 + (size_t)(r0 + 8) * vstride + col;
                if (mode == 0) {
                    *(__nv_bfloat162*)(g_yv + o0) = __floats2bfloat162_rn(acc[i][j][0], acc[i][j][1]);
                    *(__nv_bfloat162*)(g_yv + o1) = __floats2bfloat162_rn(acc[i][j][2], acc[i][j][3]);
                } else {
                    float2 yv0 = __bfloat1622float2(*(const __nv_bfloat162*)(g_yv + o0));
                    float2 yv1 = __bfloat1622float2(*(const __nv_bfloat162*)(g_yv + o1));
                    float2 x0  = *(const float2*)(x + o0);
                    float2 x1  = *(const float2*)(x + o1);
                    *(float2*)(out + o0) = make_float2(x0.x + gam * (yv0.x + acc[i][j][0]),
                                                       x0.y + gam * (yv0.y + acc[i][j][1]));
                    *(float2*)(out + o1) = make_float2(x1.x + gam * (yv1.x + acc[i][j][2]),
                                                       x1.y + gam * (yv1.y + acc[i][j][3]));
                }
            }
        }
    }
    #undef PVV_ISSUE
}

// =========================================================================
extern "C" void kernel_launch(void* const* d_in, const int* in_sizes, int n_in,
                              void* d_out, int out_size)
{
    const float* x     = (const float*)d_in[0];
    const float* Wq    = (const float*)d_in[1];
    const float* bq    = (const float*)d_in[2];
    const float* Wk    = (const float*)d_in[3];
    const float* bk    = (const float*)d_in[4];
    const float* Wv    = (const float*)d_in[5];
    const float* bv    = (const float*)d_in[6];
    const float* gamma = (const float*)d_in[7];
    float* out = (float*)d_out;
    (void)in_sizes; (void)n_in; (void)out_size;

    // All projections in ONE launch (tf32 mma, cp.async; x read once via L2)
    proj_kernel<<<dim3(5, 576), 256>>>(x, Wq, Wk, Wv, bq, bk, bv);

    // Logits, both modes in one launch (3xTF32 split mma)
    logits_kernel<<<2 * NB * NW, 256>>>();

    // Joint softmax (writes tf32-rounded probs)
    softmax_kernel<<<NT / 8, 256>>>();

    // Attention-value (tf32 mma, cp.async pipelined) + epilogue
    pv_kernel<<<NB * NW, 256>>>(x, gamma, out, 0);
    pv_kernel<<<NB * NH, 256>>>(x, gamma, out, 1);
}